// round 4
// baseline (speedup 1.0000x reference)
#include <cuda_runtime.h>
#include <cstdint>

#define EPSV 1e-5f
#define NB   16
#define CC   128
#define C2   64
#define CR   8
#define HWn  16384
#define KTOT 256
#define TPIX 128
#define KCH  32

// ---------------- device scratch (no allocations allowed) ----------------
__device__ __align__(16) float g_pooled[NB*KTOT];
__device__ __align__(16) float g_wch[NB*CC];
__device__ __align__(16) float g_W[NB*KTOT*CC];     // [n][k][o], bn_c scale folded
__device__ __align__(16) float g_beta[CC];
__device__ __align__(16) float g_chansum[NB*CC];
__device__            int   g_chanmax[NB*CC];       // float bits, g >= 0
__device__ __align__(16) float g_spsum[NB*HWn];
__device__ __align__(16) float g_spmax[NB*HWn];
__device__ __align__(16) float g_ca[NB*CC];
__device__ __align__(16) float g_sa[NB*HWn];

__device__ __forceinline__ float sigmoidf_(float x){ return 1.0f/(1.0f + expf(-x)); }

// ---------------- K1: channel-wise spatial mean of [f_vi; f_ir] ----------------
__global__ void k_pool(const float* __restrict__ fvi, const float* __restrict__ fir){
    int ch = blockIdx.x; int n = blockIdx.y; int tid = threadIdx.x;
    const float* src = (ch < CC) ? (fvi + ((size_t)(n*CC + ch))*HWn)
                                 : (fir + ((size_t)(n*CC + ch - CC))*HWn);
    const float4* s4 = (const float4*)src;
    float s = 0.f;
    for (int i = tid; i < HWn/4; i += 256){ float4 v = s4[i]; s += (v.x+v.y)+(v.z+v.w); }
    for (int d = 16; d; d >>= 1) s += __shfl_xor_sync(0xffffffffu, s, d);
    __shared__ float ws[8];
    if ((tid & 31) == 0) ws[tid >> 5] = s;
    __syncthreads();
    if (tid == 0){
        float t = 0.f;
        #pragma unroll
        for (int i = 0; i < 8; ++i) t += ws[i];
        g_pooled[n*KTOT + ch] = t * (1.0f/HWn);
    }
}

// ---------------- K2a: channel-attention MLP -> wch[n][c] ----------------
__global__ void k_wch(const float* __restrict__ ca1_w, const float* __restrict__ ca1_b,
                      const float* __restrict__ bna_g, const float* __restrict__ bna_b,
                      const float* __restrict__ bna_m, const float* __restrict__ bna_v,
                      const float* __restrict__ ca2_w, const float* __restrict__ ca2_b,
                      const float* __restrict__ bnb_g, const float* __restrict__ bnb_b,
                      const float* __restrict__ bnb_m, const float* __restrict__ bnb_v){
    int n = blockIdx.x; int tid = threadIdx.x; int lane = tid & 31; int w = tid >> 5;
    __shared__ float pool_s[KTOT];
    __shared__ float h_s[C2];
    for (int i = tid; i < KTOT; i += 256) pool_s[i] = g_pooled[n*KTOT + i];
    __syncthreads();
    for (int jj = 0; jj < 8; ++jj){
        int j = w*8 + jj;
        float s = 0.f;
        for (int k = lane; k < KTOT; k += 32) s += pool_s[k]*__ldg(&ca1_w[j*KTOT + k]);
        for (int d = 16; d; d >>= 1) s += __shfl_xor_sync(0xffffffffu, s, d);
        if (lane == 0){
            float sa = bna_g[j]*rsqrtf(bna_v[j] + EPSV);
            h_s[j] = fmaxf(0.f, (s + ca1_b[j] - bna_m[j])*sa + bna_b[j]);
        }
    }
    __syncthreads();
    if (tid < CC){
        int o = tid; float s = 0.f;
        #pragma unroll 8
        for (int j = 0; j < C2; ++j) s += h_s[j]*__ldg(&ca2_w[o*C2 + j]);
        float sb = bnb_g[o]*rsqrtf(bnb_v[o] + EPSV);
        g_wch[n*CC + o] = sigmoidf_((s + ca2_b[o] - bnb_m[o])*sb + bnb_b[o]);
    }
}

// ---- K2b: build per-batch effective weights [n][k][o] + beta, zero stats ----
__global__ void k_mkw(const float* __restrict__ cw, const float* __restrict__ c1b,
                      const float* __restrict__ bnc_g, const float* __restrict__ bnc_b,
                      const float* __restrict__ bnc_m, const float* __restrict__ bnc_v){
    int idx = blockIdx.x*256 + threadIdx.x;           // 524288 threads exactly
    int o = idx & 127; int k = (idx >> 7) & 255; int n = idx >> 15;
    float sc = bnc_g[o]*rsqrtf(bnc_v[o] + EPSV);
    int c = k & 127;
    float w1v = __ldg(&cw[o*KTOT + c]);
    float w2v = __ldg(&cw[o*KTOT + CC + c]);
    float wc  = __ldg(&g_wch[n*CC + c]);
    float val = (k < CC) ? sc*(w1v + wc*w2v) : sc*(w2v + wc*w1v);
    g_W[n*(KTOT*CC) + k*CC + o] = val;
    if (idx < CC){
        float s2 = bnc_g[idx]*rsqrtf(bnc_v[idx] + EPSV);
        g_beta[idx] = bnc_b[idx] + s2*(c1b[idx] - bnc_m[idx]);
    }
    if (idx < NB*CC){ g_chansum[idx] = 0.f; g_chanmax[idx] = 0; }
}

// ---------------- K3: main 1x1-conv GEMM + fused reductions ----------------
__global__ __launch_bounds__(256,2) void k_main(const float* __restrict__ fvi,
                                                const float* __restrict__ fir){
    __shared__ float Ws[KCH][CC];      // [k][o]  16 KB
    __shared__ float fs[KCH][TPIX];    // [k][px] 16 KB (reused for transpose)
    __shared__ float sps[TPIX];
    __shared__ int   spm[TPIX];
    int tid = threadIdx.x; int pg = tid & 15; int og = tid >> 4;
    int n = blockIdx.y; int p0 = blockIdx.x * TPIX;
    const float* fvin = fvi + (size_t)n*CC*HWn + p0;
    const float* firn = fir + (size_t)n*CC*HWn + p0;
    const float* Wn = g_W + (size_t)n*(KTOT*CC);

    if (tid < TPIX){ sps[tid] = 0.f; spm[tid] = 0; }

    float acc[8][8];
    #pragma unroll
    for (int i = 0; i < 8; ++i)
        #pragma unroll
        for (int j = 0; j < 8; ++j) acc[i][j] = 0.f;

    for (int kc = 0; kc < KTOT/KCH; ++kc){
        __syncthreads();
        int cb = kc*KCH;
        // W chunk: 32k x 128o floats, already [k][o] in gmem -> coalesced float4
        {
            const float4* src = (const float4*)(Wn + cb*CC);
            float4* dst = (float4*)&Ws[0][0];
            #pragma unroll
            for (int i = 0; i < 4; ++i) dst[tid + 256*i] = src[tid + 256*i];
        }
        // f chunk: 32 channels x 128 px
        #pragma unroll
        for (int i = 0; i < 4; ++i){
            int idx = tid + 256*i;                 // 0..1023 float4 slots
            int row = idx >> 5; int k4 = (idx & 31) << 2;
            int ch = cb + row;
            const float* src = (ch < CC) ? (fvin + (size_t)ch*HWn)
                                         : (firn + (size_t)(ch - CC)*HWn);
            *(float4*)&fs[row][k4] = *(const float4*)(src + k4);
        }
        __syncthreads();
        #pragma unroll 4
        for (int kk = 0; kk < KCH; ++kk){
            float4 w0 = *(const float4*)&Ws[kk][og*8];
            float4 w1 = *(const float4*)&Ws[kk][og*8 + 4];
            float4 f0 = *(const float4*)&fs[kk][pg*8];
            float4 f1 = *(const float4*)&fs[kk][pg*8 + 4];
            float wv[8] = {w0.x,w0.y,w0.z,w0.w,w1.x,w1.y,w1.z,w1.w};
            float fv[8] = {f0.x,f0.y,f0.z,f0.w,f1.x,f1.y,f1.z,f1.w};
            #pragma unroll
            for (int i = 0; i < 8; ++i)
                #pragma unroll
                for (int j = 0; j < 8; ++j)
                    acc[i][j] = fmaf(wv[i], fv[j], acc[i][j]);
        }
    }

    // ---- epilogue: g = relu(acc + beta), fused reductions ----
    float csum[8], cmax[8], bet[8], ssp[8], smp[8];
    #pragma unroll
    for (int i = 0; i < 8; ++i){ csum[i] = 0.f; cmax[i] = 0.f; bet[i] = __ldg(&g_beta[og*8 + i]); }
    #pragma unroll
    for (int j = 0; j < 8; ++j){ ssp[j] = 0.f; smp[j] = 0.f; }
    #pragma unroll
    for (int i = 0; i < 8; ++i)
        #pragma unroll
        for (int j = 0; j < 8; ++j){
            float gv = fmaxf(acc[i][j] + bet[i], 0.f);
            csum[i] += gv; cmax[i] = fmaxf(cmax[i], gv);
            ssp[j]  += gv; smp[j]  = fmaxf(smp[j], gv);
        }
    // combine the warp's two og-groups (lanes l and l^16 share pixels)
    #pragma unroll
    for (int j = 0; j < 8; ++j){
        ssp[j] += __shfl_xor_sync(0xffffffffu, ssp[j], 16);
        smp[j] = fmaxf(smp[j], __shfl_xor_sync(0xffffffffu, smp[j], 16));
    }
    if ((tid & 16) == 0){
        #pragma unroll
        for (int j = 0; j < 8; ++j){
            atomicAdd(&sps[pg*8 + j], ssp[j]);
            atomicMax(&spm[pg*8 + j], __float_as_int(smp[j]));
        }
    }
    __syncthreads();   // all warps done reading fs; safe to reuse for transpose
    float* cs = &fs[0][0]; float* cm = cs + CC*16;
    #pragma unroll
    for (int i = 0; i < 8; ++i){
        cs[(og*8 + i)*16 + pg] = csum[i];
        cm[(og*8 + i)*16 + pg] = cmax[i];
    }
    __syncthreads();
    if (tid < CC){
        float s = 0.f, m = 0.f;
        #pragma unroll
        for (int t = 0; t < 16; ++t){ s += cs[tid*16 + t]; m = fmaxf(m, cm[tid*16 + t]); }
        atomicAdd(&g_chansum[n*CC + tid], s);
        atomicMax(&g_chanmax[n*CC + tid], __float_as_int(m));
    } else {
        int p = tid - CC;
        g_spsum[n*HWn + p0 + p] = sps[p];
        g_spmax[n*HWn + p0 + p] = __int_as_float(spm[p]);
    }
}

// ---------------- K4a: CBAM channel attention -> ca[n][o] ----------------
__global__ void k_ca(const float* __restrict__ w1, const float* __restrict__ w2){
    __shared__ float avg_s[NB*CC], mx_s[NB*CC], hs[NB*CR];
    int tid = threadIdx.x;
    for (int i = tid; i < NB*CC; i += 256){
        avg_s[i] = g_chansum[i]*(1.0f/HWn);
        mx_s[i]  = __int_as_float(g_chanmax[i]);
    }
    __syncthreads();
    if (tid < NB*CR){
        int n = tid >> 3, r = tid & 7;
        float da = 0.f, dm = 0.f;
        for (int c = 0; c < CC; ++c){
            float wv = __ldg(&w1[r*CC + c]);
            da += avg_s[n*CC + c]*wv;
            dm += mx_s[n*CC + c]*wv;
        }
        hs[tid] = fmaxf(da, 0.f) + fmaxf(dm, 0.f);
    }
    __syncthreads();
    for (int i = tid; i < NB*CC; i += 256){
        int n = i >> 7, o = i & 127;
        float y = 0.f;
        #pragma unroll
        for (int r = 0; r < CR; ++r) y += hs[n*CR + r]*__ldg(&w2[o*CR + r]);
        g_ca[i] = sigmoidf_(y);
    }
}

// ---------------- K4b: 7x7 spatial conv + sigmoid -> sa[n][p] ----------------
__global__ void k_sa(const float* __restrict__ saw){
    __shared__ float in_s[2][22][22];
    __shared__ float w_s[98];
    int n = blockIdx.y; int t = blockIdx.x;
    int ty0 = (t >> 3)*16, tx0 = (t & 7)*16;
    int tx = threadIdx.x, ty = threadIdx.y;
    int lt = ty*16 + tx;
    if (lt < 98) w_s[lt] = saw[lt];
    for (int i = lt; i < 2*22*22; i += 256){
        int ch = i / 484; int rr = i % 484; int yy = rr / 22, xx = rr % 22;
        int gy = ty0 - 3 + yy, gx = tx0 - 3 + xx;
        float v = 0.f;
        if (gy >= 0 && gy < 128 && gx >= 0 && gx < 128){
            int off = n*HWn + gy*128 + gx;
            v = (ch == 0) ? g_spsum[off]*(1.0f/CC) : g_spmax[off];
        }
        in_s[ch][yy][xx] = v;
    }
    __syncthreads();
    float acc = 0.f;
    #pragma unroll
    for (int ch = 0; ch < 2; ++ch)
        #pragma unroll
        for (int ky = 0; ky < 7; ++ky)
            #pragma unroll
            for (int kx = 0; kx < 7; ++kx)
                acc += in_s[ch][ty + ky][tx + kx]*w_s[ch*49 + ky*7 + kx];
    g_sa[n*HWn + (ty0 + ty)*128 + tx0 + tx] = sigmoidf_(acc);
}

// ---------------- K5: final blend ----------------
__global__ void k_out(const float* __restrict__ fvi, const float* __restrict__ fir,
                      float* __restrict__ out){
    int c = blockIdx.x, n = blockIdx.y, tid = threadIdx.x;
    size_t base = ((size_t)n*CC + c)*HWn;
    float wc  = g_wch[n*CC + c];
    float cav = g_ca[n*CC + c];
    const float4* v4 = (const float4*)(fvi + base);
    const float4* i4 = (const float4*)(fir + base);
    const float4* s4 = (const float4*)(g_sa + (size_t)n*HWn);
    float4* o4 = (float4*)(out + base);
    for (int i = tid; i < HWn/4; i += 256){
        float4 a = v4[i], b = i4[i], s = s4[i];
        float4 r;
        {
            float wgt = sigmoidf_(s.x*cav);
            float fv2 = fmaf(b.x, wc, a.x), fi2 = fmaf(a.x, wc, b.x);
            r.x = fi2 + wgt*(fv2 - fi2);
        }
        {
            float wgt = sigmoidf_(s.y*cav);
            float fv2 = fmaf(b.y, wc, a.y), fi2 = fmaf(a.y, wc, b.y);
            r.y = fi2 + wgt*(fv2 - fi2);
        }
        {
            float wgt = sigmoidf_(s.z*cav);
            float fv2 = fmaf(b.z, wc, a.z), fi2 = fmaf(a.z, wc, b.z);
            r.z = fi2 + wgt*(fv2 - fi2);
        }
        {
            float wgt = sigmoidf_(s.w*cav);
            float fv2 = fmaf(b.w, wc, a.w), fi2 = fmaf(a.w, wc, b.w);
            r.w = fi2 + wgt*(fv2 - fi2);
        }
        o4[i] = r;
    }
}

// ---------------- launcher ----------------
extern "C" void kernel_launch(void* const* d_in, const int* in_sizes, int n_in,
                              void* d_out, int out_size){
    const float* fvi    = (const float*)d_in[0];
    const float* fir    = (const float*)d_in[1];
    const float* ca1_w  = (const float*)d_in[2];
    const float* ca1_b  = (const float*)d_in[3];
    const float* bna_g  = (const float*)d_in[4];
    const float* bna_b  = (const float*)d_in[5];
    const float* bna_m  = (const float*)d_in[6];
    const float* bna_v  = (const float*)d_in[7];
    const float* ca2_w  = (const float*)d_in[8];
    const float* ca2_b  = (const float*)d_in[9];
    const float* bnb_g  = (const float*)d_in[10];
    const float* bnb_b  = (const float*)d_in[11];
    const float* bnb_m  = (const float*)d_in[12];
    const float* bnb_v  = (const float*)d_in[13];
    const float* cw     = (const float*)d_in[14];
    const float* c1b    = (const float*)d_in[15];
    const float* bnc_g  = (const float*)d_in[16];
    const float* bnc_b  = (const float*)d_in[17];
    const float* bnc_m  = (const float*)d_in[18];
    const float* bnc_v  = (const float*)d_in[19];
    const float* w1     = (const float*)d_in[20];
    const float* w2     = (const float*)d_in[21];
    const float* saw    = (const float*)d_in[22];

    k_pool<<<dim3(256, NB), 256>>>(fvi, fir);
    k_wch <<<NB, 256>>>(ca1_w, ca1_b, bna_g, bna_b, bna_m, bna_v,
                        ca2_w, ca2_b, bnb_g, bnb_b, bnb_m, bnb_v);
    k_mkw <<<2048, 256>>>(cw, c1b, bnc_g, bnc_b, bnc_m, bnc_v);
    k_main<<<dim3(HWn/TPIX, NB), 256>>>(fvi, fir);
    k_ca  <<<1, 256>>>(w1, w2);
    k_sa  <<<dim3(64, NB), dim3(16, 16)>>>(saw);
    k_out <<<dim3(CC, NB), 256>>>(fvi, fir, (float*)d_out);
}

// round 6
// speedup vs baseline: 1.0396x; 1.0396x over previous
#include <cuda_runtime.h>
#include <cstdint>

#define EPSV 1e-5f
#define NB   16
#define CC   128
#define C2   64
#define CR   8
#define HWn  16384
#define KTOT 256
#define TPIX 128
#define KCH  32

typedef unsigned long long u64;
#define FMA2(d,a,b) asm("fma.rn.f32x2 %0, %1, %2, %0;" : "+l"(d) : "l"(a), "l"(b))

// ---------------- device scratch (no allocations allowed) ----------------
__device__ __align__(16) float g_pooled[NB*KTOT];
__device__ __align__(16) float g_wch[NB*CC];
__device__ __align__(16) float g_W[NB*KTOT*CC];     // [n][k][o], bn_c scale folded
__device__ __align__(16) float g_beta[CC];
__device__ __align__(16) float g_chansum[NB*CC];
__device__            int   g_chanmax[NB*CC];       // float bits, g >= 0
__device__ __align__(16) float g_spsum[NB*HWn];
__device__ __align__(16) float g_spmax[NB*HWn];
__device__ __align__(16) float g_ca[NB*CC];
__device__ __align__(16) float g_sa[NB*HWn];

__device__ __forceinline__ float sigmoidf_(float x){ return 1.0f/(1.0f + expf(-x)); }

// ---------------- K1: channel-wise spatial mean of [f_vi; f_ir] ----------------
__global__ void k_pool(const float* __restrict__ fvi, const float* __restrict__ fir){
    int ch = blockIdx.x; int n = blockIdx.y; int tid = threadIdx.x;
    const float* src = (ch < CC) ? (fvi + ((size_t)(n*CC + ch))*HWn)
                                 : (fir + ((size_t)(n*CC + ch - CC))*HWn);
    const float4* s4 = (const float4*)src;
    float s = 0.f;
    for (int i = tid; i < HWn/4; i += 256){ float4 v = s4[i]; s += (v.x+v.y)+(v.z+v.w); }
    for (int d = 16; d; d >>= 1) s += __shfl_xor_sync(0xffffffffu, s, d);
    __shared__ float ws[8];
    if ((tid & 31) == 0) ws[tid >> 5] = s;
    __syncthreads();
    if (tid == 0){
        float t = 0.f;
        #pragma unroll
        for (int i = 0; i < 8; ++i) t += ws[i];
        g_pooled[n*KTOT + ch] = t * (1.0f/HWn);
    }
}

// ---------------- K2a: channel-attention MLP -> wch[n][c] ----------------
__global__ void k_wch(const float* __restrict__ ca1_w, const float* __restrict__ ca1_b,
                      const float* __restrict__ bna_g, const float* __restrict__ bna_b,
                      const float* __restrict__ bna_m, const float* __restrict__ bna_v,
                      const float* __restrict__ ca2_w, const float* __restrict__ ca2_b,
                      const float* __restrict__ bnb_g, const float* __restrict__ bnb_b,
                      const float* __restrict__ bnb_m, const float* __restrict__ bnb_v){
    int n = blockIdx.x; int tid = threadIdx.x; int lane = tid & 31; int w = tid >> 5;
    __shared__ float pool_s[KTOT];
    __shared__ float h_s[C2];
    for (int i = tid; i < KTOT; i += 256) pool_s[i] = g_pooled[n*KTOT + i];
    __syncthreads();
    for (int jj = 0; jj < 8; ++jj){
        int j = w*8 + jj;
        float s = 0.f;
        for (int k = lane; k < KTOT; k += 32) s += pool_s[k]*__ldg(&ca1_w[j*KTOT + k]);
        for (int d = 16; d; d >>= 1) s += __shfl_xor_sync(0xffffffffu, s, d);
        if (lane == 0){
            float sa = bna_g[j]*rsqrtf(bna_v[j] + EPSV);
            h_s[j] = fmaxf(0.f, (s + ca1_b[j] - bna_m[j])*sa + bna_b[j]);
        }
    }
    __syncthreads();
    if (tid < CC){
        int o = tid; float s = 0.f;
        #pragma unroll 8
        for (int j = 0; j < C2; ++j) s += h_s[j]*__ldg(&ca2_w[o*C2 + j]);
        float sb = bnb_g[o]*rsqrtf(bnb_v[o] + EPSV);
        g_wch[n*CC + o] = sigmoidf_((s + ca2_b[o] - bnb_m[o])*sb + bnb_b[o]);
    }
}

// ---- K2b: build per-batch effective weights [n][k][o] + beta, zero stats ----
__global__ void k_mkw(const float* __restrict__ cw, const float* __restrict__ c1b,
                      const float* __restrict__ bnc_g, const float* __restrict__ bnc_b,
                      const float* __restrict__ bnc_m, const float* __restrict__ bnc_v){
    int idx = blockIdx.x*256 + threadIdx.x;           // 524288 threads exactly
    int o = idx & 127; int k = (idx >> 7) & 255; int n = idx >> 15;
    float sc = bnc_g[o]*rsqrtf(bnc_v[o] + EPSV);
    int c = k & 127;
    float w1v = __ldg(&cw[o*KTOT + c]);
    float w2v = __ldg(&cw[o*KTOT + CC + c]);
    float wc  = __ldg(&g_wch[n*CC + c]);
    float val = (k < CC) ? sc*(w1v + wc*w2v) : sc*(w2v + wc*w1v);
    g_W[n*(KTOT*CC) + k*CC + o] = val;
    if (idx < CC){
        float s2 = bnc_g[idx]*rsqrtf(bnc_v[idx] + EPSV);
        g_beta[idx] = bnc_b[idx] + s2*(c1b[idx] - bnc_m[idx]);
    }
    if (idx < NB*CC){ g_chansum[idx] = 0.f; g_chanmax[idx] = 0; }
}

// ---------------- K3: main 1x1-conv GEMM + fused reductions (f32x2) ----------------
__global__ __launch_bounds__(256,2) void k_main(const float* __restrict__ fvi,
                                                const float* __restrict__ fir){
    __shared__ float Ws[KCH][CC];      // [k][o]  16 KB
    __shared__ float fs[KCH][TPIX];    // [k][px] 16 KB (reused for transpose)
    __shared__ float sps[TPIX];
    __shared__ int   spm[TPIX];
    int tid = threadIdx.x; int pg = tid & 15; int og = tid >> 4;
    int n = blockIdx.y; int p0 = blockIdx.x * TPIX;
    const float* fvin = fvi + (size_t)n*CC*HWn + p0;
    const float* firn = fir + (size_t)n*CC*HWn + p0;
    const float* Wn = g_W + (size_t)n*(KTOT*CC);

    if (tid < TPIX){ sps[tid] = 0.f; spm[tid] = 0; }

    u64 acc2[8][4];
    #pragma unroll
    for (int i = 0; i < 8; ++i)
        #pragma unroll
        for (int j = 0; j < 4; ++j) acc2[i][j] = 0ull;

    for (int kc = 0; kc < KTOT/KCH; ++kc){
        __syncthreads();
        int cb = kc*KCH;
        // W chunk: 32k x 128o floats, already [k][o] in gmem -> coalesced float4
        {
            const float4* src = (const float4*)(Wn + cb*CC);
            float4* dst = (float4*)&Ws[0][0];
            #pragma unroll
            for (int i = 0; i < 4; ++i) dst[tid + 256*i] = src[tid + 256*i];
        }
        // f chunk: 32 channels x 128 px
        #pragma unroll
        for (int i = 0; i < 4; ++i){
            int idx = tid + 256*i;                 // 0..1023 float4 slots
            int row = idx >> 5; int k4 = (idx & 31) << 2;
            int ch = cb + row;
            const float* src = (ch < CC) ? (fvin + (size_t)ch*HWn)
                                         : (firn + (size_t)(ch - CC)*HWn);
            *(float4*)&fs[row][k4] = *(const float4*)(src + k4);
        }
        __syncthreads();
        #pragma unroll 4
        for (int kk = 0; kk < KCH; ++kk){
            float4 w0 = *(const float4*)&Ws[kk][og*8];
            float4 w1 = *(const float4*)&Ws[kk][og*8 + 4];
            const u64* fp = (const u64*)&fs[kk][pg*8];   // 32B-aligned
            u64 b0 = fp[0], b1 = fp[1], b2 = fp[2], b3 = fp[3];
            float wv[8] = {w0.x,w0.y,w0.z,w0.w,w1.x,w1.y,w1.z,w1.w};
            #pragma unroll
            for (int i = 0; i < 8; ++i){
                u64 wd;
                asm("mov.b64 %0, {%1, %1};" : "=l"(wd) : "f"(wv[i]));
                FMA2(acc2[i][0], wd, b0);
                FMA2(acc2[i][1], wd, b1);
                FMA2(acc2[i][2], wd, b2);
                FMA2(acc2[i][3], wd, b3);
            }
        }
    }

    // ---- epilogue: g = relu(acc + beta), fused reductions ----
    float csum[8], cmax[8], bet[8], ssp[8], smp[8];
    #pragma unroll
    for (int i = 0; i < 8; ++i){ csum[i] = 0.f; cmax[i] = 0.f; bet[i] = __ldg(&g_beta[og*8 + i]); }
    #pragma unroll
    for (int j = 0; j < 8; ++j){ ssp[j] = 0.f; smp[j] = 0.f; }
    #pragma unroll
    for (int jp = 0; jp < 4; ++jp)
        #pragma unroll
        for (int i = 0; i < 8; ++i){
            u64 a = acc2[i][jp];
            float gx = fmaxf(__uint_as_float((unsigned)a)         + bet[i], 0.f);
            float gy = fmaxf(__uint_as_float((unsigned)(a >> 32)) + bet[i], 0.f);
            csum[i] += gx + gy; cmax[i] = fmaxf(cmax[i], fmaxf(gx, gy));
            ssp[2*jp]   += gx;  smp[2*jp]   = fmaxf(smp[2*jp],   gx);
            ssp[2*jp+1] += gy;  smp[2*jp+1] = fmaxf(smp[2*jp+1], gy);
        }
    // combine the warp's two og-groups (lanes l and l^16 share pixels)
    #pragma unroll
    for (int j = 0; j < 8; ++j){
        ssp[j] += __shfl_xor_sync(0xffffffffu, ssp[j], 16);
        smp[j] = fmaxf(smp[j], __shfl_xor_sync(0xffffffffu, smp[j], 16));
    }
    if ((tid & 16) == 0){
        #pragma unroll
        for (int j = 0; j < 8; ++j){
            atomicAdd(&sps[pg*8 + j], ssp[j]);
            atomicMax(&spm[pg*8 + j], __float_as_int(smp[j]));
        }
    }
    __syncthreads();   // all warps done reading fs; safe to reuse for transpose
    float* cs = &fs[0][0]; float* cm = cs + CC*16;
    #pragma unroll
    for (int i = 0; i < 8; ++i){
        cs[(og*8 + i)*16 + pg] = csum[i];
        cm[(og*8 + i)*16 + pg] = cmax[i];
    }
    __syncthreads();
    if (tid < CC){
        float s = 0.f, m = 0.f;
        #pragma unroll
        for (int t = 0; t < 16; ++t){ s += cs[tid*16 + t]; m = fmaxf(m, cm[tid*16 + t]); }
        atomicAdd(&g_chansum[n*CC + tid], s);
        atomicMax(&g_chanmax[n*CC + tid], __float_as_int(m));
    } else {
        int p = tid - CC;
        g_spsum[n*HWn + p0 + p] = sps[p];
        g_spmax[n*HWn + p0 + p] = __int_as_float(spm[p]);
    }
}

// ---------------- K4a: CBAM channel attention -> ca[n][o] ----------------
__global__ void k_ca(const float* __restrict__ w1, const float* __restrict__ w2){
    __shared__ float avg_s[NB*CC], mx_s[NB*CC], hs[NB*CR];
    int tid = threadIdx.x;
    for (int i = tid; i < NB*CC; i += 256){
        avg_s[i] = g_chansum[i]*(1.0f/HWn);
        mx_s[i]  = __int_as_float(g_chanmax[i]);
    }
    __syncthreads();
    if (tid < NB*CR){
        int n = tid >> 3, r = tid & 7;
        float da = 0.f, dm = 0.f;
        for (int c = 0; c < CC; ++c){
            float wv = __ldg(&w1[r*CC + c]);
            da += avg_s[n*CC + c]*wv;
            dm += mx_s[n*CC + c]*wv;
        }
        hs[tid] = fmaxf(da, 0.f) + fmaxf(dm, 0.f);
    }
    __syncthreads();
    for (int i = tid; i < NB*CC; i += 256){
        int n = i >> 7, o = i & 127;
        float y = 0.f;
        #pragma unroll
        for (int r = 0; r < CR; ++r) y += hs[n*CR + r]*__ldg(&w2[o*CR + r]);
        g_ca[i] = sigmoidf_(y);
    }
}

// ---------------- K4b: 7x7 spatial conv + sigmoid -> sa[n][p] ----------------
__global__ void k_sa(const float* __restrict__ saw){
    __shared__ float in_s[2][22][22];
    __shared__ float w_s[98];
    int n = blockIdx.y; int t = blockIdx.x;
    int ty0 = (t >> 3)*16, tx0 = (t & 7)*16;
    int tx = threadIdx.x, ty = threadIdx.y;
    int lt = ty*16 + tx;
    if (lt < 98) w_s[lt] = saw[lt];
    for (int i = lt; i < 2*22*22; i += 256){
        int ch = i / 484; int rr = i % 484; int yy = rr / 22, xx = rr % 22;
        int gy = ty0 - 3 + yy, gx = tx0 - 3 + xx;
        float v = 0.f;
        if (gy >= 0 && gy < 128 && gx >= 0 && gx < 128){
            int off = n*HWn + gy*128 + gx;
            v = (ch == 0) ? g_spsum[off]*(1.0f/CC) : g_spmax[off];
        }
        in_s[ch][yy][xx] = v;
    }
    __syncthreads();
    float acc = 0.f;
    #pragma unroll
    for (int ch = 0; ch < 2; ++ch)
        #pragma unroll
        for (int ky = 0; ky < 7; ++ky)
            #pragma unroll
            for (int kx = 0; kx < 7; ++kx)
                acc += in_s[ch][ty + ky][tx + kx]*w_s[ch*49 + ky*7 + kx];
    g_sa[n*HWn + (ty0 + ty)*128 + tx0 + tx] = sigmoidf_(acc);
}

// ---------------- K5: final blend ----------------
__global__ void k_out(const float* __restrict__ fvi, const float* __restrict__ fir,
                      float* __restrict__ out){
    int c = blockIdx.x, n = blockIdx.y, tid = threadIdx.x;
    size_t base = ((size_t)n*CC + c)*HWn;
    float wc  = g_wch[n*CC + c];
    float cav = g_ca[n*CC + c];
    const float4* v4 = (const float4*)(fvi + base);
    const float4* i4 = (const float4*)(fir + base);
    const float4* s4 = (const float4*)(g_sa + (size_t)n*HWn);
    float4* o4 = (float4*)(out + base);
    for (int i = tid; i < HWn/4; i += 256){
        float4 a = v4[i], b = i4[i], s = s4[i];
        float4 r;
        {
            float wgt = sigmoidf_(s.x*cav);
            float fv2 = fmaf(b.x, wc, a.x), fi2 = fmaf(a.x, wc, b.x);
            r.x = fi2 + wgt*(fv2 - fi2);
        }
        {
            float wgt = sigmoidf_(s.y*cav);
            float fv2 = fmaf(b.y, wc, a.y), fi2 = fmaf(a.y, wc, b.y);
            r.y = fi2 + wgt*(fv2 - fi2);
        }
        {
            float wgt = sigmoidf_(s.z*cav);
            float fv2 = fmaf(b.z, wc, a.z), fi2 = fmaf(a.z, wc, b.z);
            r.z = fi2 + wgt*(fv2 - fi2);
        }
        {
            float wgt = sigmoidf_(s.w*cav);
            float fv2 = fmaf(b.w, wc, a.w), fi2 = fmaf(a.w, wc, b.w);
            r.w = fi2 + wgt*(fv2 - fi2);
        }
        o4[i] = r;
    }
}

// ---------------- launcher ----------------
extern "C" void kernel_launch(void* const* d_in, const int* in_sizes, int n_in,
                              void* d_out, int out_size){
    const float* fvi    = (const float*)d_in[0];
    const float* fir    = (const float*)d_in[1];
    const float* ca1_w  = (const float*)d_in[2];
    const float* ca1_b  = (const float*)d_in[3];
    const float* bna_g  = (const float*)d_in[4];
    const float* bna_b  = (const float*)d_in[5];
    const float* bna_m  = (const float*)d_in[6];
    const float* bna_v  = (const float*)d_in[7];
    const float* ca2_w  = (const float*)d_in[8];
    const float* ca2_b  = (const float*)d_in[9];
    const float* bnb_g  = (const float*)d_in[10];
    const float* bnb_b  = (const float*)d_in[11];
    const float* bnb_m  = (const float*)d_in[12];
    const float* bnb_v  = (const float*)d_in[13];
    const float* cw     = (const float*)d_in[14];
    const float* c1b    = (const float*)d_in[15];
    const float* bnc_g  = (const float*)d_in[16];
    const float* bnc_b  = (const float*)d_in[17];
    const float* bnc_m  = (const float*)d_in[18];
    const float* bnc_v  = (const float*)d_in[19];
    const float* w1     = (const float*)d_in[20];
    const float* w2     = (const float*)d_in[21];
    const float* saw    = (const float*)d_in[22];

    k_pool<<<dim3(256, NB), 256>>>(fvi, fir);
    k_wch <<<NB, 256>>>(ca1_w, ca1_b, bna_g, bna_b, bna_m, bna_v,
                        ca2_w, ca2_b, bnb_g, bnb_b, bnb_m, bnb_v);
    k_mkw <<<2048, 256>>>(cw, c1b, bnc_g, bnc_b, bnc_m, bnc_v);
    k_main<<<dim3(HWn/TPIX, NB), 256>>>(fvi, fir);
    k_ca  <<<1, 256>>>(w1, w2);
    k_sa  <<<dim3(64, NB), dim3(16, 16)>>>(saw);
    k_out <<<dim3(CC, NB), 256>>>(fvi, fir, (float*)d_out);
}

// round 7
// speedup vs baseline: 1.0795x; 1.0384x over previous
#include <cuda_runtime.h>
#include <cstdint>

#define EPSV 1e-5f
#define NB   16
#define CC   128
#define C2   64
#define CR   8
#define HWn  16384
#define KTOT 256
#define TPIX 128
#define KCH  16
#define NCH  (KTOT/KCH)

typedef unsigned long long u64;
#define FMA2(d,a,b) asm("fma.rn.f32x2 %0, %1, %2, %0;" : "+l"(d) : "l"(a), "l"(b))

__device__ __forceinline__ void cp16(void* s, const void* g){
    unsigned sa = (unsigned)__cvta_generic_to_shared(s);
    asm volatile("cp.async.cg.shared.global [%0], [%1], 16;" :: "r"(sa), "l"(g));
}
#define CP_COMMIT() asm volatile("cp.async.commit_group;")
#define CP_WAIT(n)  asm volatile("cp.async.wait_group %0;" :: "n"(n))

// ---------------- device scratch (no allocations allowed) ----------------
__device__ __align__(16) float g_pooled[NB*KTOT];
__device__ __align__(16) float g_wch[NB*CC];
__device__ __align__(16) float g_W[NB*KTOT*CC];     // [n][k][o], bn_c scale folded
__device__ __align__(16) float g_beta[CC];
__device__ __align__(16) float g_chansum[NB*CC];
__device__            int   g_chanmax[NB*CC];       // float bits, g >= 0
__device__ __align__(16) float g_spsum[NB*HWn];
__device__ __align__(16) float g_spmax[NB*HWn];
__device__ __align__(16) float g_ca[NB*CC];
__device__ __align__(16) float g_sa[NB*HWn];

__device__ __forceinline__ float sigmoidf_(float x){ return 1.0f/(1.0f + expf(-x)); }

// ---------------- K1: channel-wise spatial mean of [f_vi; f_ir] ----------------
__global__ void k_pool(const float* __restrict__ fvi, const float* __restrict__ fir){
    int ch = blockIdx.x; int n = blockIdx.y; int tid = threadIdx.x;
    const float* src = (ch < CC) ? (fvi + ((size_t)(n*CC + ch))*HWn)
                                 : (fir + ((size_t)(n*CC + ch - CC))*HWn);
    const float4* s4 = (const float4*)src;
    float s = 0.f;
    for (int i = tid; i < HWn/4; i += 256){ float4 v = s4[i]; s += (v.x+v.y)+(v.z+v.w); }
    for (int d = 16; d; d >>= 1) s += __shfl_xor_sync(0xffffffffu, s, d);
    __shared__ float ws[8];
    if ((tid & 31) == 0) ws[tid >> 5] = s;
    __syncthreads();
    if (tid == 0){
        float t = 0.f;
        #pragma unroll
        for (int i = 0; i < 8; ++i) t += ws[i];
        g_pooled[n*KTOT + ch] = t * (1.0f/HWn);
    }
}

// ---------------- K2a: channel-attention MLP -> wch[n][c] ----------------
__global__ void k_wch(const float* __restrict__ ca1_w, const float* __restrict__ ca1_b,
                      const float* __restrict__ bna_g, const float* __restrict__ bna_b,
                      const float* __restrict__ bna_m, const float* __restrict__ bna_v,
                      const float* __restrict__ ca2_w, const float* __restrict__ ca2_b,
                      const float* __restrict__ bnb_g, const float* __restrict__ bnb_b,
                      const float* __restrict__ bnb_m, const float* __restrict__ bnb_v){
    int n = blockIdx.x; int tid = threadIdx.x; int lane = tid & 31; int w = tid >> 5;
    __shared__ float pool_s[KTOT];
    __shared__ float h_s[C2];
    for (int i = tid; i < KTOT; i += 256) pool_s[i] = g_pooled[n*KTOT + i];
    __syncthreads();
    for (int jj = 0; jj < 8; ++jj){
        int j = w*8 + jj;
        float s = 0.f;
        for (int k = lane; k < KTOT; k += 32) s += pool_s[k]*__ldg(&ca1_w[j*KTOT + k]);
        for (int d = 16; d; d >>= 1) s += __shfl_xor_sync(0xffffffffu, s, d);
        if (lane == 0){
            float sa = bna_g[j]*rsqrtf(bna_v[j] + EPSV);
            h_s[j] = fmaxf(0.f, (s + ca1_b[j] - bna_m[j])*sa + bna_b[j]);
        }
    }
    __syncthreads();
    if (tid < CC){
        int o = tid; float s = 0.f;
        #pragma unroll 8
        for (int j = 0; j < C2; ++j) s += h_s[j]*__ldg(&ca2_w[o*C2 + j]);
        float sb = bnb_g[o]*rsqrtf(bnb_v[o] + EPSV);
        g_wch[n*CC + o] = sigmoidf_((s + ca2_b[o] - bnb_m[o])*sb + bnb_b[o]);
    }
}

// ---- K2b: build per-batch effective weights [n][k][o] + beta, zero stats ----
__global__ void k_mkw(const float* __restrict__ cw, const float* __restrict__ c1b,
                      const float* __restrict__ bnc_g, const float* __restrict__ bnc_b,
                      const float* __restrict__ bnc_m, const float* __restrict__ bnc_v){
    int idx = blockIdx.x*256 + threadIdx.x;           // 524288 threads exactly
    int o = idx & 127; int k = (idx >> 7) & 255; int n = idx >> 15;
    float sc = bnc_g[o]*rsqrtf(bnc_v[o] + EPSV);
    int c = k & 127;
    float w1v = __ldg(&cw[o*KTOT + c]);
    float w2v = __ldg(&cw[o*KTOT + CC + c]);
    float wc  = __ldg(&g_wch[n*CC + c]);
    float val = (k < CC) ? sc*(w1v + wc*w2v) : sc*(w2v + wc*w1v);
    g_W[n*(KTOT*CC) + k*CC + o] = val;
    if (idx < CC){
        float s2 = bnc_g[idx]*rsqrtf(bnc_v[idx] + EPSV);
        g_beta[idx] = bnc_b[idx] + s2*(c1b[idx] - bnc_m[idx]);
    }
    if (idx < NB*CC){ g_chansum[idx] = 0.f; g_chanmax[idx] = 0; }
}

// ------- K3: main 1x1-conv GEMM + fused reductions (f32x2, cp.async pipeline) -------
__global__ __launch_bounds__(256,2) void k_main(const float* __restrict__ fvi,
                                                const float* __restrict__ fir){
    __shared__ __align__(16) float Ws[2][KCH][CC];    // 16 KB
    __shared__ __align__(16) float fs[2][KCH][TPIX];  // 16 KB (reused for transpose)
    __shared__ float sps[TPIX];
    __shared__ int   spm[TPIX];
    int tid = threadIdx.x; int pg = tid & 15; int og = tid >> 4;
    int n = blockIdx.y; int p0 = blockIdx.x * TPIX;
    const float* fvin = fvi + (size_t)n*CC*HWn + p0;
    const float* firn = fir + (size_t)n*CC*HWn + p0;
    const float* Wn = g_W + (size_t)n*(KTOT*CC);

    if (tid < TPIX){ sps[tid] = 0.f; spm[tid] = 0; }

    u64 acc2[8][4];
    #pragma unroll
    for (int i = 0; i < 8; ++i)
        #pragma unroll
        for (int j = 0; j < 4; ++j) acc2[i][j] = 0ull;

    // async-copy one chunk (16 k-rows of W and f) into buffer `buf`
    auto load_chunk = [&](int kc, int buf){
        int cb = kc*KCH;
        const float4* wsrc = (const float4*)(Wn + cb*CC);   // 512 float4
        float4* wdst = (float4*)&Ws[buf][0][0];
        #pragma unroll
        for (int i = 0; i < 2; ++i)
            cp16(&wdst[tid + 256*i], &wsrc[tid + 256*i]);
        #pragma unroll
        for (int i = 0; i < 2; ++i){
            int idx = tid + 256*i;                 // 0..511 float4 slots
            int row = idx >> 5; int k4 = (idx & 31) << 2;
            int ch = cb + row;
            const float* src = (ch < CC) ? (fvin + (size_t)ch*HWn)
                                         : (firn + (size_t)(ch - CC)*HWn);
            cp16(&fs[buf][row][k4], src + k4);
        }
    };

    load_chunk(0, 0); CP_COMMIT();
    for (int kc = 0; kc < NCH; ++kc){
        int buf = kc & 1;
        if (kc + 1 < NCH){ load_chunk(kc + 1, (kc + 1) & 1); CP_COMMIT(); CP_WAIT(1); }
        else             { CP_WAIT(0); }
        __syncthreads();          // chunk kc visible to all warps
        #pragma unroll 4
        for (int kk = 0; kk < KCH; ++kk){
            float4 w0 = *(const float4*)&Ws[buf][kk][og*8];
            float4 w1 = *(const float4*)&Ws[buf][kk][og*8 + 4];
            const u64* fp = (const u64*)&fs[buf][kk][pg*8];   // 32B-aligned
            u64 b0 = fp[0], b1 = fp[1], b2 = fp[2], b3 = fp[3];
            float wv[8] = {w0.x,w0.y,w0.z,w0.w,w1.x,w1.y,w1.z,w1.w};
            #pragma unroll
            for (int i = 0; i < 8; ++i){
                u64 wd;
                asm("mov.b64 %0, {%1, %1};" : "=l"(wd) : "f"(wv[i]));
                FMA2(acc2[i][0], wd, b0);
                FMA2(acc2[i][1], wd, b1);
                FMA2(acc2[i][2], wd, b2);
                FMA2(acc2[i][3], wd, b3);
            }
        }
        __syncthreads();          // all warps done with buf before it is refilled
    }

    // ---- epilogue: g = relu(acc + beta), fused reductions ----
    float csum[8], cmax[8], bet[8], ssp[8], smp[8];
    #pragma unroll
    for (int i = 0; i < 8; ++i){ csum[i] = 0.f; cmax[i] = 0.f; bet[i] = __ldg(&g_beta[og*8 + i]); }
    #pragma unroll
    for (int j = 0; j < 8; ++j){ ssp[j] = 0.f; smp[j] = 0.f; }
    #pragma unroll
    for (int jp = 0; jp < 4; ++jp)
        #pragma unroll
        for (int i = 0; i < 8; ++i){
            u64 a = acc2[i][jp];
            float gx = fmaxf(__uint_as_float((unsigned)a)         + bet[i], 0.f);
            float gy = fmaxf(__uint_as_float((unsigned)(a >> 32)) + bet[i], 0.f);
            csum[i] += gx + gy; cmax[i] = fmaxf(cmax[i], fmaxf(gx, gy));
            ssp[2*jp]   += gx;  smp[2*jp]   = fmaxf(smp[2*jp],   gx);
            ssp[2*jp+1] += gy;  smp[2*jp+1] = fmaxf(smp[2*jp+1], gy);
        }
    // combine the warp's two og-groups (lanes l and l^16 share pixels)
    #pragma unroll
    for (int j = 0; j < 8; ++j){
        ssp[j] += __shfl_xor_sync(0xffffffffu, ssp[j], 16);
        smp[j] = fmaxf(smp[j], __shfl_xor_sync(0xffffffffu, smp[j], 16));
    }
    if ((tid & 16) == 0){
        #pragma unroll
        for (int j = 0; j < 8; ++j){
            atomicAdd(&sps[pg*8 + j], ssp[j]);
            atomicMax(&spm[pg*8 + j], __float_as_int(smp[j]));
        }
    }
    // channel stats: transpose through smem (reuse fs: 2*16*128 = 4096 floats)
    float* cs = &fs[0][0][0]; float* cm = cs + CC*16;
    #pragma unroll
    for (int i = 0; i < 8; ++i){
        cs[(og*8 + i)*16 + pg] = csum[i];
        cm[(og*8 + i)*16 + pg] = cmax[i];
    }
    __syncthreads();
    if (tid < CC){
        float s = 0.f, m = 0.f;
        #pragma unroll
        for (int t = 0; t < 16; ++t){ s += cs[tid*16 + t]; m = fmaxf(m, cm[tid*16 + t]); }
        atomicAdd(&g_chansum[n*CC + tid], s);
        atomicMax(&g_chanmax[n*CC + tid], __float_as_int(m));
    } else {
        int p = tid - CC;
        g_spsum[n*HWn + p0 + p] = sps[p];
        g_spmax[n*HWn + p0 + p] = __int_as_float(spm[p]);
    }
}

// ---------------- K4a: CBAM channel attention -> ca[n][o] ----------------
__global__ void k_ca(const float* __restrict__ w1, const float* __restrict__ w2){
    __shared__ float avg_s[NB*CC], mx_s[NB*CC], hs[NB*CR];
    int tid = threadIdx.x;
    for (int i = tid; i < NB*CC; i += 256){
        avg_s[i] = g_chansum[i]*(1.0f/HWn);
        mx_s[i]  = __int_as_float(g_chanmax[i]);
    }
    __syncthreads();
    if (tid < NB*CR){
        int n = tid >> 3, r = tid & 7;
        float da = 0.f, dm = 0.f;
        for (int c = 0; c < CC; ++c){
            float wv = __ldg(&w1[r*CC + c]);
            da += avg_s[n*CC + c]*wv;
            dm += mx_s[n*CC + c]*wv;
        }
        hs[tid] = fmaxf(da, 0.f) + fmaxf(dm, 0.f);
    }
    __syncthreads();
    for (int i = tid; i < NB*CC; i += 256){
        int n = i >> 7, o = i & 127;
        float y = 0.f;
        #pragma unroll
        for (int r = 0; r < CR; ++r) y += hs[n*CR + r]*__ldg(&w2[o*CR + r]);
        g_ca[i] = sigmoidf_(y);
    }
}

// ---------------- K4b: 7x7 spatial conv + sigmoid -> sa[n][p] ----------------
__global__ void k_sa(const float* __restrict__ saw){
    __shared__ float in_s[2][22][22];
    __shared__ float w_s[98];
    int n = blockIdx.y; int t = blockIdx.x;
    int ty0 = (t >> 3)*16, tx0 = (t & 7)*16;
    int tx = threadIdx.x, ty = threadIdx.y;
    int lt = ty*16 + tx;
    if (lt < 98) w_s[lt] = saw[lt];
    for (int i = lt; i < 2*22*22; i += 256){
        int ch = i / 484; int rr = i % 484; int yy = rr / 22, xx = rr % 22;
        int gy = ty0 - 3 + yy, gx = tx0 - 3 + xx;
        float v = 0.f;
        if (gy >= 0 && gy < 128 && gx >= 0 && gx < 128){
            int off = n*HWn + gy*128 + gx;
            v = (ch == 0) ? g_spsum[off]*(1.0f/CC) : g_spmax[off];
        }
        in_s[ch][yy][xx] = v;
    }
    __syncthreads();
    float acc = 0.f;
    #pragma unroll
    for (int ch = 0; ch < 2; ++ch)
        #pragma unroll
        for (int ky = 0; ky < 7; ++ky)
            #pragma unroll
            for (int kx = 0; kx < 7; ++kx)
                acc += in_s[ch][ty + ky][tx + kx]*w_s[ch*49 + ky*7 + kx];
    g_sa[n*HWn + (ty0 + ty)*128 + tx0 + tx] = sigmoidf_(acc);
}

// ---------------- K5: final blend ----------------
__global__ void k_out(const float* __restrict__ fvi, const float* __restrict__ fir,
                      float* __restrict__ out){
    int c = blockIdx.x, n = blockIdx.y, tid = threadIdx.x;
    size_t base = ((size_t)n*CC + c)*HWn;
    float wc  = g_wch[n*CC + c];
    float cav = g_ca[n*CC + c];
    const float4* v4 = (const float4*)(fvi + base);
    const float4* i4 = (const float4*)(fir + base);
    const float4* s4 = (const float4*)(g_sa + (size_t)n*HWn);
    float4* o4 = (float4*)(out + base);
    for (int i = tid; i < HWn/4; i += 256){
        float4 a = v4[i], b = i4[i], s = s4[i];
        float4 r;
        {
            float wgt = sigmoidf_(s.x*cav);
            float fv2 = fmaf(b.x, wc, a.x), fi2 = fmaf(a.x, wc, b.x);
            r.x = fi2 + wgt*(fv2 - fi2);
        }
        {
            float wgt = sigmoidf_(s.y*cav);
            float fv2 = fmaf(b.y, wc, a.y), fi2 = fmaf(a.y, wc, b.y);
            r.y = fi2 + wgt*(fv2 - fi2);
        }
        {
            float wgt = sigmoidf_(s.z*cav);
            float fv2 = fmaf(b.z, wc, a.z), fi2 = fmaf(a.z, wc, b.z);
            r.z = fi2 + wgt*(fv2 - fi2);
        }
        {
            float wgt = sigmoidf_(s.w*cav);
            float fv2 = fmaf(b.w, wc, a.w), fi2 = fmaf(a.w, wc, b.w);
            r.w = fi2 + wgt*(fv2 - fi2);
        }
        o4[i] = r;
    }
}

// ---------------- launcher ----------------
extern "C" void kernel_launch(void* const* d_in, const int* in_sizes, int n_in,
                              void* d_out, int out_size){
    const float* fvi    = (const float*)d_in[0];
    const float* fir    = (const float*)d_in[1];
    const float* ca1_w  = (const float*)d_in[2];
    const float* ca1_b  = (const float*)d_in[3];
    const float* bna_g  = (const float*)d_in[4];
    const float* bna_b  = (const float*)d_in[5];
    const float* bna_m  = (const float*)d_in[6];
    const float* bna_v  = (const float*)d_in[7];
    const float* ca2_w  = (const float*)d_in[8];
    const float* ca2_b  = (const float*)d_in[9];
    const float* bnb_g  = (const float*)d_in[10];
    const float* bnb_b  = (const float*)d_in[11];
    const float* bnb_m  = (const float*)d_in[12];
    const float* bnb_v  = (const float*)d_in[13];
    const float* cw     = (const float*)d_in[14];
    const float* c1b    = (const float*)d_in[15];
    const float* bnc_g  = (const float*)d_in[16];
    const float* bnc_b  = (const float*)d_in[17];
    const float* bnc_m  = (const float*)d_in[18];
    const float* bnc_v  = (const float*)d_in[19];
    const float* w1     = (const float*)d_in[20];
    const float* w2     = (const float*)d_in[21];
    const float* saw    = (const float*)d_in[22];

    k_pool<<<dim3(256, NB), 256>>>(fvi, fir);
    k_wch <<<NB, 256>>>(ca1_w, ca1_b, bna_g, bna_b, bna_m, bna_v,
                        ca2_w, ca2_b, bnb_g, bnb_b, bnb_m, bnb_v);
    k_mkw <<<2048, 256>>>(cw, c1b, bnc_g, bnc_b, bnc_m, bnc_v);
    k_main<<<dim3(HWn/TPIX, NB), 256>>>(fvi, fir);
    k_ca  <<<1, 256>>>(w1, w2);
    k_sa  <<<dim3(64, NB), dim3(16, 16)>>>(saw);
    k_out <<<dim3(CC, NB), 256>>>(fvi, fir, (float*)d_out);
}

// round 13
// speedup vs baseline: 2.0313x; 1.8818x over previous
#include <cuda_runtime.h>
#include <cstdint>

#define EPSV 1e-5f
#define NB   16
#define CC   128
#define C2   64
#define CR   8
#define HWn  16384
#define TPIX 128
#define KTOT 256
#define KCH  16

typedef unsigned long long u64;

__device__ __forceinline__ void cp16(void* s, const void* g){
    unsigned sa = (unsigned)__cvta_generic_to_shared(s);
    asm volatile("cp.async.cg.shared.global [%0], [%1], 16;" :: "r"(sa), "l"(g));
}
#define CP_COMMIT() asm volatile("cp.async.commit_group;")
#define CP_WAIT1()  asm volatile("cp.async.wait_group 1;")
#define CP_WAIT0()  asm volatile("cp.async.wait_group 0;")

// ---------------- device scratch (no allocations allowed) ----------------
__device__ __align__(16) float g_pooled[NB*KTOT];
__device__ __align__(16) float g_wch[NB*CC];
__device__ __align__(16) float g_W[NB*KTOT*CC];     // per-n 32768 floats, MMA-fragment order, tf32-rounded
__device__ __align__(16) float g_beta[CC];
__device__ __align__(16) float g_chansum[NB*CC];
__device__            int   g_chanmax[NB*CC];       // float bits, g >= 0
__device__ __align__(16) float g_spsum[NB*HWn];
__device__ __align__(16) float g_spmax[NB*HWn];
__device__ __align__(16) float g_ca[NB*CC];
__device__ __align__(16) float g_sa[NB*HWn];

__device__ __forceinline__ float sigmoidf_(float x){ return 1.0f/(1.0f + expf(-x)); }

// ---------------- K1: channel-wise spatial mean of [f_vi; f_ir] ----------------
__global__ void k_pool(const float* __restrict__ fvi, const float* __restrict__ fir){
    int ch = blockIdx.x; int n = blockIdx.y; int tid = threadIdx.x;
    const float* src = (ch < CC) ? (fvi + ((size_t)(n*CC + ch))*HWn)
                                 : (fir + ((size_t)(n*CC + ch - CC))*HWn);
    const float4* s4 = (const float4*)src;
    float s = 0.f;
    for (int i = tid; i < HWn/4; i += 256){ float4 v = s4[i]; s += (v.x+v.y)+(v.z+v.w); }
    for (int d = 16; d; d >>= 1) s += __shfl_xor_sync(0xffffffffu, s, d);
    __shared__ float ws[8];
    if ((tid & 31) == 0) ws[tid >> 5] = s;
    __syncthreads();
    if (tid == 0){
        float t = 0.f;
        #pragma unroll
        for (int i = 0; i < 8; ++i) t += ws[i];
        g_pooled[n*KTOT + ch] = t * (1.0f/HWn);
    }
}

// ---------------- K2a: channel-attention MLP -> wch[n][c] ----------------
__global__ void k_wch(const float* __restrict__ ca1_w, const float* __restrict__ ca1_b,
                      const float* __restrict__ bna_g, const float* __restrict__ bna_b,
                      const float* __restrict__ bna_m, const float* __restrict__ bna_v,
                      const float* __restrict__ ca2_w, const float* __restrict__ ca2_b,
                      const float* __restrict__ bnb_g, const float* __restrict__ bnb_b,
                      const float* __restrict__ bnb_m, const float* __restrict__ bnb_v){
    int n = blockIdx.x; int tid = threadIdx.x; int lane = tid & 31; int w = tid >> 5;
    __shared__ float pool_s[KTOT];
    __shared__ float h_s[C2];
    for (int i = tid; i < KTOT; i += 256) pool_s[i] = g_pooled[n*KTOT + i];
    __syncthreads();
    for (int jj = 0; jj < 8; ++jj){
        int j = w*8 + jj;
        float s = 0.f;
        for (int k = lane; k < KTOT; k += 32) s += pool_s[k]*__ldg(&ca1_w[j*KTOT + k]);
        for (int d = 16; d; d >>= 1) s += __shfl_xor_sync(0xffffffffu, s, d);
        if (lane == 0){
            float sa = bna_g[j]*rsqrtf(bna_v[j] + EPSV);
            h_s[j] = fmaxf(0.f, (s + ca1_b[j] - bna_m[j])*sa + bna_b[j]);
        }
    }
    __syncthreads();
    if (tid < CC){
        int o = tid; float s = 0.f;
        #pragma unroll 8
        for (int j = 0; j < C2; ++j) s += h_s[j]*__ldg(&ca2_w[o*C2 + j]);
        float sb = bnb_g[o]*rsqrtf(bnb_v[o] + EPSV);
        g_wch[n*CC + o] = sigmoidf_((s + ca2_b[o] - bnb_m[o])*sb + bnb_b[o]);
    }
}

// ---- K2b: effective weights -> tf32-rounded, MMA A-fragment order ----
// per n: [chunk c(16)][s(2)][mt(8)][lane(32)][elem(4)]; elem: a0..a3 of m16n8k8
__global__ void k_mkw(const float* __restrict__ cw, const float* __restrict__ c1b,
                      const float* __restrict__ bnc_g, const float* __restrict__ bnc_b,
                      const float* __restrict__ bnc_m, const float* __restrict__ bnc_v){
    int idx = blockIdx.x*256 + threadIdx.x;           // 524288 threads exactly
    int o = idx & 127; int k = (idx >> 7) & 255; int n = idx >> 15;
    float sc = bnc_g[o]*rsqrtf(bnc_v[o] + EPSV);
    int c = k & 127;
    float w1v = __ldg(&cw[o*KTOT + c]);
    float w2v = __ldg(&cw[o*KTOT + CC + c]);
    float wc  = __ldg(&g_wch[n*CC + c]);
    float val = (k < CC) ? sc*(w1v + wc*w2v) : sc*(w2v + wc*w1v);
    uint32_t tv; asm("cvt.rna.tf32.f32 %0, %1;" : "=r"(tv) : "f"(val));
    int ch  = k >> 4;                 // chunk
    int s   = (k >> 3) & 1;
    int klo = k & 3, khi = (k >> 2) & 1;
    int mt  = o >> 4;
    int rlo = o & 7, rhi = (o >> 3) & 1;
    int lane = rlo*4 + klo, elem = khi*2 + rhi;
    g_W[(size_t)n*32768 + ch*2048 + ((s*8 + mt)*32 + lane)*4 + elem] = __uint_as_float(tv);
    if (idx < CC){
        float s2 = bnc_g[idx]*rsqrtf(bnc_v[idx] + EPSV);
        g_beta[idx] = bnc_b[idx] + s2*(c1b[idx] - bnc_m[idx]);
    }
    if (idx < NB*CC){ g_chansum[idx] = 0.f; g_chanmax[idx] = 0; }
}

// -------- K3: tf32 mma.sync GEMM, D[128o x 128px] per CTA, fused reductions --------
__global__ __launch_bounds__(256,2) void k_main(const float* __restrict__ fvi,
                                                const float* __restrict__ fir){
    __shared__ __align__(16) float sb[8192];      // [buf][W 2048][B 2048]
    __shared__ float cs[CC]; __shared__ int cmi[CC];
    __shared__ float psp[2][TPIX], pmp[2][TPIX];

    int tid = threadIdx.x; int w = tid >> 5, lane = tid & 31;
    int klo = lane & 3, pxl = lane >> 2;
    int ob = (w & 1)*64, pb = (w >> 1)*32;
    int n = blockIdx.y; int p0 = blockIdx.x * TPIX;
    const float* fvin = fvi + (size_t)n*CC*HWn + p0;
    const float* firn = fir + (size_t)n*CC*HWn + p0;
    const float* Wn = g_W + (size_t)n*32768;

    if (tid < CC){ cs[tid] = 0.f; cmi[tid] = 0; }

    float acc[4][4][4];
    #pragma unroll
    for (int i = 0; i < 4; ++i)
        #pragma unroll
        for (int j = 0; j < 4; ++j)
            #pragma unroll
            for (int e = 0; e < 4; ++e) acc[i][j][e] = 0.f;

    auto load_chunk = [&](int c, int buf){
        float* wd = sb + buf*4096;
        const float* ws = Wn + c*2048;
        cp16(wd + tid*4,        ws + tid*4);
        cp16(wd + (tid+256)*4,  ws + (tid+256)*4);
        float* bd = sb + buf*4096 + 2048;
        #pragma unroll
        for (int i = 0; i < 2; ++i){
            int slot = tid + 256*i;              // 0..511 16B slots
            int k = slot >> 5; int px0 = (slot & 31) << 2;
            int chn = c*KCH + k;
            const float* src = (chn < CC) ? (fvin + (size_t)chn*HWn + px0)
                                          : (firn + (size_t)(chn - CC)*HWn + px0);
            cp16(bd + k*128 + (px0 ^ ((k & 3) << 3)), src);
        }
    };

    load_chunk(0, 0); CP_COMMIT();
    for (int c = 0; c < 16; ++c){
        int buf = c & 1;
        if (c < 15){ load_chunk(c + 1, buf ^ 1); CP_COMMIT(); CP_WAIT1(); }
        else CP_WAIT0();
        __syncthreads();
        const float* Wsb = sb + buf*4096;
        const float* Fsb = Wsb + 2048;
        #pragma unroll
        for (int s = 0; s < 2; ++s){
            uint32_t a[4][4];
            #pragma unroll
            for (int mt = 0; mt < 4; ++mt){
                float4 av = *(const float4*)&Wsb[((s*8 + (w & 1)*4 + mt)*32 + lane)*4];
                a[mt][0] = __float_as_uint(av.x); a[mt][1] = __float_as_uint(av.y);
                a[mt][2] = __float_as_uint(av.z); a[mt][3] = __float_as_uint(av.w);
            }
            uint32_t b[4][2];
            #pragma unroll
            for (int nt = 0; nt < 4; ++nt){
                int xo = (pb + nt*8 + pxl) ^ (klo << 3);
                float f0 = Fsb[(s*8 + klo)*128 + xo];
                float f1 = Fsb[(s*8 + klo + 4)*128 + xo];
                asm("cvt.rna.tf32.f32 %0, %1;" : "=r"(b[nt][0]) : "f"(f0));
                asm("cvt.rna.tf32.f32 %0, %1;" : "=r"(b[nt][1]) : "f"(f1));
            }
            #pragma unroll
            for (int mt = 0; mt < 4; ++mt)
                #pragma unroll
                for (int nt = 0; nt < 4; ++nt)
                    asm("mma.sync.aligned.m16n8k8.row.col.f32.tf32.tf32.f32 "
                        "{%0,%1,%2,%3},{%4,%5,%6,%7},{%8,%9},{%0,%1,%2,%3};"
                        : "+f"(acc[mt][nt][0]), "+f"(acc[mt][nt][1]),
                          "+f"(acc[mt][nt][2]), "+f"(acc[mt][nt][3])
                        : "r"(a[mt][0]), "r"(a[mt][1]), "r"(a[mt][2]), "r"(a[mt][3]),
                          "r"(b[nt][0]), "r"(b[nt][1]));
        }
        __syncthreads();
    }

    // ---- epilogue: relu(acc+beta) in-place ----
    #pragma unroll
    for (int mt = 0; mt < 4; ++mt){
        float b0 = __ldg(&g_beta[ob + mt*16 + pxl]);
        float b1 = __ldg(&g_beta[ob + mt*16 + pxl + 8]);
        #pragma unroll
        for (int nt = 0; nt < 4; ++nt){
            acc[mt][nt][0] = fmaxf(acc[mt][nt][0] + b0, 0.f);
            acc[mt][nt][1] = fmaxf(acc[mt][nt][1] + b0, 0.f);
            acc[mt][nt][2] = fmaxf(acc[mt][nt][2] + b1, 0.f);
            acc[mt][nt][3] = fmaxf(acc[mt][nt][3] + b1, 0.f);
        }
    }
    // channel partials: rows r=pxl (+8) per mt; reduce over cols (lanes xor 1,2)
    {
        float rs[8], rm[8];
        #pragma unroll
        for (int mt = 0; mt < 4; ++mt){
            float s0 = 0.f, s1 = 0.f, m0 = 0.f, m1 = 0.f;
            #pragma unroll
            for (int nt = 0; nt < 4; ++nt){
                s0 += acc[mt][nt][0] + acc[mt][nt][1];
                s1 += acc[mt][nt][2] + acc[mt][nt][3];
                m0 = fmaxf(m0, fmaxf(acc[mt][nt][0], acc[mt][nt][1]));
                m1 = fmaxf(m1, fmaxf(acc[mt][nt][2], acc[mt][nt][3]));
            }
            rs[mt*2] = s0; rs[mt*2+1] = s1; rm[mt*2] = m0; rm[mt*2+1] = m1;
        }
        #pragma unroll
        for (int i = 0; i < 8; ++i){
            rs[i] += __shfl_xor_sync(0xffffffffu, rs[i], 1);
            rs[i] += __shfl_xor_sync(0xffffffffu, rs[i], 2);
            rm[i] = fmaxf(rm[i], __shfl_xor_sync(0xffffffffu, rm[i], 1));
            rm[i] = fmaxf(rm[i], __shfl_xor_sync(0xffffffffu, rm[i], 2));
        }
        if (klo == 0){
            #pragma unroll
            for (int mt = 0; mt < 4; ++mt)
                #pragma unroll
                for (int h = 0; h < 2; ++h){
                    int o = ob + mt*16 + h*8 + pxl;
                    atomicAdd(&cs[o], rs[mt*2 + h]);
                    atomicMax(&cmi[o], __float_as_int(rm[mt*2 + h]));
                }
        }
    }
    // px partials: cols 2*klo+j per nt; reduce over rows (lanes xor 4,8,16)
    {
        float qs[8], qm[8];
        #pragma unroll
        for (int nt = 0; nt < 4; ++nt)
            #pragma unroll
            for (int j = 0; j < 2; ++j){
                float s = 0.f, m = 0.f;
                #pragma unroll
                for (int mt = 0; mt < 4; ++mt){
                    s += acc[mt][nt][j] + acc[mt][nt][j+2];
                    m = fmaxf(m, fmaxf(acc[mt][nt][j], acc[mt][nt][j+2]));
                }
                qs[nt*2 + j] = s; qm[nt*2 + j] = m;
            }
        #pragma unroll
        for (int i = 0; i < 8; ++i){
            qs[i] += __shfl_xor_sync(0xffffffffu, qs[i], 4);
            qs[i] += __shfl_xor_sync(0xffffffffu, qs[i], 8);
            qs[i] += __shfl_xor_sync(0xffffffffu, qs[i], 16);
            qm[i] = fmaxf(qm[i], __shfl_xor_sync(0xffffffffu, qm[i], 4));
            qm[i] = fmaxf(qm[i], __shfl_xor_sync(0xffffffffu, qm[i], 8));
            qm[i] = fmaxf(qm[i], __shfl_xor_sync(0xffffffffu, qm[i], 16));
        }
        if (lane < 4){
            #pragma unroll
            for (int nt = 0; nt < 4; ++nt)
                #pragma unroll
                for (int j = 0; j < 2; ++j){
                    int col = pb + nt*8 + 2*lane + j;
                    psp[w & 1][col] = qs[nt*2 + j];
                    pmp[w & 1][col] = qm[nt*2 + j];
                }
        }
    }
    __syncthreads();
    if (tid < TPIX){
        g_spsum[n*HWn + p0 + tid] = psp[0][tid] + psp[1][tid];
        g_spmax[n*HWn + p0 + tid] = fmaxf(pmp[0][tid], pmp[1][tid]);
    } else {
        int o = tid - TPIX;
        atomicAdd(&g_chansum[n*CC + o], cs[o]);
        atomicMax(&g_chanmax[n*CC + o], cmi[o]);
    }
}

// ---------------- K4a: CBAM channel attention -> ca[n][o] ----------------
__global__ void k_ca(const float* __restrict__ w1, const float* __restrict__ w2){
    __shared__ float avg_s[NB*CC], mx_s[NB*CC], hs[NB*CR];
    int tid = threadIdx.x;
    for (int i = tid; i < NB*CC; i += 256){
        avg_s[i] = g_chansum[i]*(1.0f/HWn);
        mx_s[i]  = __int_as_float(g_chanmax[i]);
    }
    __syncthreads();
    if (tid < NB*CR){
        int n = tid >> 3, r = tid & 7;
        float da = 0.f, dm = 0.f;
        for (int c = 0; c < CC; ++c){
            float wv = __ldg(&w1[r*CC + c]);
            da += avg_s[n*CC + c]*wv;
            dm += mx_s[n*CC + c]*wv;
        }
        hs[tid] = fmaxf(da, 0.f) + fmaxf(dm, 0.f);
    }
    __syncthreads();
    for (int i = tid; i < NB*CC; i += 256){
        int n = i >> 7, o = i & 127;
        float y = 0.f;
        #pragma unroll
        for (int r = 0; r < CR; ++r) y += hs[n*CR + r]*__ldg(&w2[o*CR + r]);
        g_ca[i] = sigmoidf_(y);
    }
}

// ---------------- K4b: 7x7 spatial conv + sigmoid -> sa[n][p] ----------------
__global__ void k_sa(const float* __restrict__ saw){
    __shared__ float in_s[2][22][22];
    __shared__ float w_s[98];
    int n = blockIdx.y; int t = blockIdx.x;
    int ty0 = (t >> 3)*16, tx0 = (t & 7)*16;
    int tx = threadIdx.x, ty = threadIdx.y;
    int lt = ty*16 + tx;
    if (lt < 98) w_s[lt] = saw[lt];
    for (int i = lt; i < 2*22*22; i += 256){
        int ch = i / 484; int rr = i % 484; int yy = rr / 22, xx = rr % 22;
        int gy = ty0 - 3 + yy, gx = tx0 - 3 + xx;
        float v = 0.f;
        if (gy >= 0 && gy < 128 && gx >= 0 && gx < 128){
            int off = n*HWn + gy*128 + gx;
            v = (ch == 0) ? g_spsum[off]*(1.0f/CC) : g_spmax[off];
        }
        in_s[ch][yy][xx] = v;
    }
    __syncthreads();
    float acc = 0.f;
    #pragma unroll
    for (int ch = 0; ch < 2; ++ch)
        #pragma unroll
        for (int ky = 0; ky < 7; ++ky)
            #pragma unroll
            for (int kx = 0; kx < 7; ++kx)
                acc += in_s[ch][ty + ky][tx + kx]*w_s[ch*49 + ky*7 + kx];
    g_sa[n*HWn + (ty0 + ty)*128 + tx0 + tx] = sigmoidf_(acc);
}

// ---------------- K5: final blend ----------------
__global__ void k_out(const float* __restrict__ fvi, const float* __restrict__ fir,
                      float* __restrict__ out){
    int c = blockIdx.x, n = blockIdx.y, tid = threadIdx.x;
    size_t base = ((size_t)n*CC + c)*HWn;
    float wc  = g_wch[n*CC + c];
    float cav = g_ca[n*CC + c];
    const float4* v4 = (const float4*)(fvi + base);
    const float4* i4 = (const float4*)(fir + base);
    const float4* s4 = (const float4*)(g_sa + (size_t)n*HWn);
    float4* o4 = (float4*)(out + base);
    for (int i = tid; i < HWn/4; i += 256){
        float4 a = v4[i], b = i4[i], s = s4[i];
        float4 r;
        {
            float wgt = sigmoidf_(s.x*cav);
            float fv2 = fmaf(b.x, wc, a.x), fi2 = fmaf(a.x, wc, b.x);
            r.x = fi2 + wgt*(fv2 - fi2);
        }
        {
            float wgt = sigmoidf_(s.y*cav);
            float fv2 = fmaf(b.y, wc, a.y), fi2 = fmaf(a.y, wc, b.y);
            r.y = fi2 + wgt*(fv2 - fi2);
        }
        {
            float wgt = sigmoidf_(s.z*cav);
            float fv2 = fmaf(b.z, wc, a.z), fi2 = fmaf(a.z, wc, b.z);
            r.z = fi2 + wgt*(fv2 - fi2);
        }
        {
            float wgt = sigmoidf_(s.w*cav);
            float fv2 = fmaf(b.w, wc, a.w), fi2 = fmaf(a.w, wc, b.w);
            r.w = fi2 + wgt*(fv2 - fi2);
        }
        o4[i] = r;
    }
}

// ---------------- launcher ----------------
extern "C" void kernel_launch(void* const* d_in, const int* in_sizes, int n_in,
                              void* d_out, int out_size){
    const float* fvi    = (const float*)d_in[0];
    const float* fir    = (const float*)d_in[1];
    const float* ca1_w  = (const float*)d_in[2];
    const float* ca1_b  = (const float*)d_in[3];
    const float* bna_g  = (const float*)d_in[4];
    const float* bna_b  = (const float*)d_in[5];
    const float* bna_m  = (const float*)d_in[6];
    const float* bna_v  = (const float*)d_in[7];
    const float* ca2_w  = (const float*)d_in[8];
    const float* ca2_b  = (const float*)d_in[9];
    const float* bnb_g  = (const float*)d_in[10];
    const float* bnb_b  = (const float*)d_in[11];
    const float* bnb_m  = (const float*)d_in[12];
    const float* bnb_v  = (const float*)d_in[13];
    const float* cw     = (const float*)d_in[14];
    const float* c1b    = (const float*)d_in[15];
    const float* bnc_g  = (const float*)d_in[16];
    const float* bnc_b  = (const float*)d_in[17];
    const float* bnc_m  = (const float*)d_in[18];
    const float* bnc_v  = (const float*)d_in[19];
    const float* w1     = (const float*)d_in[20];
    const float* w2     = (const float*)d_in[21];
    const float* saw    = (const float*)d_in[22];

    k_pool<<<dim3(256, NB), 256>>>(fvi, fir);
    k_wch <<<NB, 256>>>(ca1_w, ca1_b, bna_g, bna_b, bna_m, bna_v,
                        ca2_w, ca2_b, bnb_g, bnb_b, bnb_m, bnb_v);
    k_mkw <<<2048, 256>>>(cw, c1b, bnc_g, bnc_b, bnc_m, bnc_v);
    k_main<<<dim3(HWn/TPIX, NB), 256>>>(fvi, fir);
    k_ca  <<<1, 256>>>(w1, w2);
    k_sa  <<<dim3(64, NB), dim3(16, 16)>>>(saw);
    k_out <<<dim3(CC, NB), 256>>>(fvi, fir, (float*)d_out);
}

// round 14
// speedup vs baseline: 2.0768x; 1.0224x over previous
#include <cuda_runtime.h>
#include <cstdint>

#define EPSV 1e-5f
#define NB   16
#define CC   128
#define C2   64
#define CR   8
#define HWn  16384
#define TPIX 128
#define KTOT 256
#define KCH  16

typedef unsigned long long u64;

__device__ __forceinline__ void cp16(void* s, const void* g){
    unsigned sa = (unsigned)__cvta_generic_to_shared(s);
    asm volatile("cp.async.cg.shared.global [%0], [%1], 16;" :: "r"(sa), "l"(g));
}
#define CP_COMMIT() asm volatile("cp.async.commit_group;")
#define CP_WAIT1()  asm volatile("cp.async.wait_group 1;")
#define CP_WAIT0()  asm volatile("cp.async.wait_group 0;")

// ---------------- device scratch (no allocations allowed) ----------------
__device__ __align__(16) float g_pooled[NB*KTOT];
__device__ __align__(16) float g_wch[NB*CC];
__device__ __align__(16) float g_W[NB*KTOT*CC];     // per-n 32768 floats, MMA-fragment order, tf32-rounded
__device__ __align__(16) float g_beta[CC];
__device__ __align__(16) float g_chansum[NB*CC];
__device__            int   g_chanmax[NB*CC];       // float bits, g >= 0
__device__ __align__(16) float g_spsum[NB*HWn];
__device__ __align__(16) float g_spmax[NB*HWn];
__device__ __align__(16) float g_ca[NB*CC];
__device__ __align__(16) float g_sa[NB*HWn];

__device__ __forceinline__ float sigmoidf_(float x){ return 1.0f/(1.0f + expf(-x)); }

// ---------------- K1: channel-wise spatial mean of [f_vi; f_ir] ----------------
__global__ void k_pool(const float* __restrict__ fvi, const float* __restrict__ fir){
    int ch = blockIdx.x; int n = blockIdx.y; int tid = threadIdx.x;
    const float* src = (ch < CC) ? (fvi + ((size_t)(n*CC + ch))*HWn)
                                 : (fir + ((size_t)(n*CC + ch - CC))*HWn);
    const float4* s4 = (const float4*)src;
    float s = 0.f;
    for (int i = tid; i < HWn/4; i += 256){ float4 v = s4[i]; s += (v.x+v.y)+(v.z+v.w); }
    for (int d = 16; d; d >>= 1) s += __shfl_xor_sync(0xffffffffu, s, d);
    __shared__ float ws[8];
    if ((tid & 31) == 0) ws[tid >> 5] = s;
    __syncthreads();
    if (tid == 0){
        float t = 0.f;
        #pragma unroll
        for (int i = 0; i < 8; ++i) t += ws[i];
        g_pooled[n*KTOT + ch] = t * (1.0f/HWn);
    }
}

// ---------------- K2a: channel-attention MLP -> wch[n][c] ----------------
__global__ void k_wch(const float* __restrict__ ca1_w, const float* __restrict__ ca1_b,
                      const float* __restrict__ bna_g, const float* __restrict__ bna_b,
                      const float* __restrict__ bna_m, const float* __restrict__ bna_v,
                      const float* __restrict__ ca2_w, const float* __restrict__ ca2_b,
                      const float* __restrict__ bnb_g, const float* __restrict__ bnb_b,
                      const float* __restrict__ bnb_m, const float* __restrict__ bnb_v){
    int n = blockIdx.x; int tid = threadIdx.x; int lane = tid & 31; int w = tid >> 5;
    __shared__ float pool_s[KTOT];
    __shared__ float h_s[C2];
    for (int i = tid; i < KTOT; i += 256) pool_s[i] = g_pooled[n*KTOT + i];
    __syncthreads();
    for (int jj = 0; jj < 8; ++jj){
        int j = w*8 + jj;
        float s = 0.f;
        for (int k = lane; k < KTOT; k += 32) s += pool_s[k]*__ldg(&ca1_w[j*KTOT + k]);
        for (int d = 16; d; d >>= 1) s += __shfl_xor_sync(0xffffffffu, s, d);
        if (lane == 0){
            float sa = bna_g[j]*rsqrtf(bna_v[j] + EPSV);
            h_s[j] = fmaxf(0.f, (s + ca1_b[j] - bna_m[j])*sa + bna_b[j]);
        }
    }
    __syncthreads();
    if (tid < CC){
        int o = tid; float s = 0.f;
        #pragma unroll 8
        for (int j = 0; j < C2; ++j) s += h_s[j]*__ldg(&ca2_w[o*C2 + j]);
        float sb = bnb_g[o]*rsqrtf(bnb_v[o] + EPSV);
        g_wch[n*CC + o] = sigmoidf_((s + ca2_b[o] - bnb_m[o])*sb + bnb_b[o]);
    }
}

// ---- K2b: effective weights -> tf32-rounded, MMA A-fragment order ----
// per n: [chunk c(16)][s(2)][mt(8)][lane(32)][elem(4)]; elem: a0..a3 of m16n8k8
__global__ void k_mkw(const float* __restrict__ cw, const float* __restrict__ c1b,
                      const float* __restrict__ bnc_g, const float* __restrict__ bnc_b,
                      const float* __restrict__ bnc_m, const float* __restrict__ bnc_v){
    int idx = blockIdx.x*256 + threadIdx.x;           // 524288 threads exactly
    int o = idx & 127; int k = (idx >> 7) & 255; int n = idx >> 15;
    float sc = bnc_g[o]*rsqrtf(bnc_v[o] + EPSV);
    int c = k & 127;
    float w1v = __ldg(&cw[o*KTOT + c]);
    float w2v = __ldg(&cw[o*KTOT + CC + c]);
    float wc  = __ldg(&g_wch[n*CC + c]);
    float val = (k < CC) ? sc*(w1v + wc*w2v) : sc*(w2v + wc*w1v);
    uint32_t tv; asm("cvt.rna.tf32.f32 %0, %1;" : "=r"(tv) : "f"(val));
    int ch  = k >> 4;                 // chunk
    int s   = (k >> 3) & 1;
    int klo = k & 3, khi = (k >> 2) & 1;
    int mt  = o >> 4;
    int rlo = o & 7, rhi = (o >> 3) & 1;
    int lane = rlo*4 + klo, elem = khi*2 + rhi;
    g_W[(size_t)n*32768 + ch*2048 + ((s*8 + mt)*32 + lane)*4 + elem] = __uint_as_float(tv);
    if (idx < CC){
        float s2 = bnc_g[idx]*rsqrtf(bnc_v[idx] + EPSV);
        g_beta[idx] = bnc_b[idx] + s2*(c1b[idx] - bnc_m[idx]);
    }
    if (idx < NB*CC){ g_chansum[idx] = 0.f; g_chanmax[idx] = 0; }
}

// -------- K3: tf32 mma.sync GEMM, D[128o x 128px] per CTA, fused reductions --------
__global__ __launch_bounds__(256,2) void k_main(const float* __restrict__ fvi,
                                                const float* __restrict__ fir){
    __shared__ __align__(16) float sb[8192];      // [buf][W 2048][B 2048]
    __shared__ float cs[CC]; __shared__ int cmi[CC];
    __shared__ float psp[2][TPIX], pmp[2][TPIX];

    int tid = threadIdx.x; int w = tid >> 5, lane = tid & 31;
    int klo = lane & 3, pxl = lane >> 2;
    int ob = (w & 1)*64, pb = (w >> 1)*32;
    int n = blockIdx.y; int p0 = blockIdx.x * TPIX;
    const float* fvin = fvi + (size_t)n*CC*HWn + p0;
    const float* firn = fir + (size_t)n*CC*HWn + p0;
    const float* Wn = g_W + (size_t)n*32768;

    if (tid < CC){ cs[tid] = 0.f; cmi[tid] = 0; }

    float acc[4][4][4];
    #pragma unroll
    for (int i = 0; i < 4; ++i)
        #pragma unroll
        for (int j = 0; j < 4; ++j)
            #pragma unroll
            for (int e = 0; e < 4; ++e) acc[i][j][e] = 0.f;

    auto load_chunk = [&](int c, int buf){
        float* wd = sb + buf*4096;
        const float* ws = Wn + c*2048;
        cp16(wd + tid*4,        ws + tid*4);
        cp16(wd + (tid+256)*4,  ws + (tid+256)*4);
        float* bd = sb + buf*4096 + 2048;
        #pragma unroll
        for (int i = 0; i < 2; ++i){
            int slot = tid + 256*i;              // 0..511 16B slots
            int k = slot >> 5; int px0 = (slot & 31) << 2;
            int chn = c*KCH + k;
            const float* src = (chn < CC) ? (fvin + (size_t)chn*HWn + px0)
                                          : (firn + (size_t)(chn - CC)*HWn + px0);
            cp16(bd + k*128 + (px0 ^ ((k & 3) << 3)), src);
        }
    };

    load_chunk(0, 0); CP_COMMIT();
    #pragma unroll 2
    for (int c = 0; c < 16; ++c){
        int buf = c & 1;
        if (c < 15){ load_chunk(c + 1, buf ^ 1); CP_COMMIT(); CP_WAIT1(); }
        else CP_WAIT0();
        __syncthreads();
        const float* Wsb = sb + buf*4096;
        const float* Fsb = Wsb + 2048;
        #pragma unroll
        for (int s = 0; s < 2; ++s){
            uint32_t a[4][4];
            #pragma unroll
            for (int mt = 0; mt < 4; ++mt){
                float4 av = *(const float4*)&Wsb[((s*8 + (w & 1)*4 + mt)*32 + lane)*4];
                a[mt][0] = __float_as_uint(av.x); a[mt][1] = __float_as_uint(av.y);
                a[mt][2] = __float_as_uint(av.z); a[mt][3] = __float_as_uint(av.w);
            }
            uint32_t b[4][2];
            #pragma unroll
            for (int nt = 0; nt < 4; ++nt){
                int xo = (pb + nt*8 + pxl) ^ (klo << 3);
                // raw f32 bits: tensor core reads the tf32 subset (truncation),
                // saves 2 ALU cvts per fragment pair on the critical path
                b[nt][0] = __float_as_uint(Fsb[(s*8 + klo)*128 + xo]);
                b[nt][1] = __float_as_uint(Fsb[(s*8 + klo + 4)*128 + xo]);
            }
            #pragma unroll
            for (int mt = 0; mt < 4; ++mt)
                #pragma unroll
                for (int nt = 0; nt < 4; ++nt)
                    asm("mma.sync.aligned.m16n8k8.row.col.f32.tf32.tf32.f32 "
                        "{%0,%1,%2,%3},{%4,%5,%6,%7},{%8,%9},{%0,%1,%2,%3};"
                        : "+f"(acc[mt][nt][0]), "+f"(acc[mt][nt][1]),
                          "+f"(acc[mt][nt][2]), "+f"(acc[mt][nt][3])
                        : "r"(a[mt][0]), "r"(a[mt][1]), "r"(a[mt][2]), "r"(a[mt][3]),
                          "r"(b[nt][0]), "r"(b[nt][1]));
        }
        __syncthreads();
    }

    // ---- epilogue: relu(acc+beta) in-place ----
    #pragma unroll
    for (int mt = 0; mt < 4; ++mt){
        float b0 = __ldg(&g_beta[ob + mt*16 + pxl]);
        float b1 = __ldg(&g_beta[ob + mt*16 + pxl + 8]);
        #pragma unroll
        for (int nt = 0; nt < 4; ++nt){
            acc[mt][nt][0] = fmaxf(acc[mt][nt][0] + b0, 0.f);
            acc[mt][nt][1] = fmaxf(acc[mt][nt][1] + b0, 0.f);
            acc[mt][nt][2] = fmaxf(acc[mt][nt][2] + b1, 0.f);
            acc[mt][nt][3] = fmaxf(acc[mt][nt][3] + b1, 0.f);
        }
    }
    // channel partials: rows r=pxl (+8) per mt; reduce over cols (lanes xor 1,2)
    {
        float rs[8], rm[8];
        #pragma unroll
        for (int mt = 0; mt < 4; ++mt){
            float s0 = 0.f, s1 = 0.f, m0 = 0.f, m1 = 0.f;
            #pragma unroll
            for (int nt = 0; nt < 4; ++nt){
                s0 += acc[mt][nt][0] + acc[mt][nt][1];
                s1 += acc[mt][nt][2] + acc[mt][nt][3];
                m0 = fmaxf(m0, fmaxf(acc[mt][nt][0], acc[mt][nt][1]));
                m1 = fmaxf(m1, fmaxf(acc[mt][nt][2], acc[mt][nt][3]));
            }
            rs[mt*2] = s0; rs[mt*2+1] = s1; rm[mt*2] = m0; rm[mt*2+1] = m1;
        }
        #pragma unroll
        for (int i = 0; i < 8; ++i){
            rs[i] += __shfl_xor_sync(0xffffffffu, rs[i], 1);
            rs[i] += __shfl_xor_sync(0xffffffffu, rs[i], 2);
            rm[i] = fmaxf(rm[i], __shfl_xor_sync(0xffffffffu, rm[i], 1));
            rm[i] = fmaxf(rm[i], __shfl_xor_sync(0xffffffffu, rm[i], 2));
        }
        if (klo == 0){
            #pragma unroll
            for (int mt = 0; mt < 4; ++mt)
                #pragma unroll
                for (int h = 0; h < 2; ++h){
                    int o = ob + mt*16 + h*8 + pxl;
                    atomicAdd(&cs[o], rs[mt*2 + h]);
                    atomicMax(&cmi[o], __float_as_int(rm[mt*2 + h]));
                }
        }
    }
    // px partials: cols 2*klo+j per nt; reduce over rows (lanes xor 4,8,16)
    {
        float qs[8], qm[8];
        #pragma unroll
        for (int nt = 0; nt < 4; ++nt)
            #pragma unroll
            for (int j = 0; j < 2; ++j){
                float s = 0.f, m = 0.f;
                #pragma unroll
                for (int mt = 0; mt < 4; ++mt){
                    s += acc[mt][nt][j] + acc[mt][nt][j+2];
                    m = fmaxf(m, fmaxf(acc[mt][nt][j], acc[mt][nt][j+2]));
                }
                qs[nt*2 + j] = s; qm[nt*2 + j] = m;
            }
        #pragma unroll
        for (int i = 0; i < 8; ++i){
            qs[i] += __shfl_xor_sync(0xffffffffu, qs[i], 4);
            qs[i] += __shfl_xor_sync(0xffffffffu, qs[i], 8);
            qs[i] += __shfl_xor_sync(0xffffffffu, qs[i], 16);
            qm[i] = fmaxf(qm[i], __shfl_xor_sync(0xffffffffu, qm[i], 4));
            qm[i] = fmaxf(qm[i], __shfl_xor_sync(0xffffffffu, qm[i], 8));
            qm[i] = fmaxf(qm[i], __shfl_xor_sync(0xffffffffu, qm[i], 16));
        }
        if (lane < 4){
            #pragma unroll
            for (int nt = 0; nt < 4; ++nt)
                #pragma unroll
                for (int j = 0; j < 2; ++j){
                    int col = pb + nt*8 + 2*lane + j;
                    psp[w & 1][col] = qs[nt*2 + j];
                    pmp[w & 1][col] = qm[nt*2 + j];
                }
        }
    }
    __syncthreads();
    if (tid < TPIX){
        g_spsum[n*HWn + p0 + tid] = psp[0][tid] + psp[1][tid];
        g_spmax[n*HWn + p0 + tid] = fmaxf(pmp[0][tid], pmp[1][tid]);
    } else {
        int o = tid - TPIX;
        atomicAdd(&g_chansum[n*CC + o], cs[o]);
        atomicMax(&g_chanmax[n*CC + o], cmi[o]);
    }
}

// ---------------- K4a: CBAM channel attention -> ca[n][o] ----------------
__global__ void k_ca(const float* __restrict__ w1, const float* __restrict__ w2){
    __shared__ float avg_s[NB*CC], mx_s[NB*CC], hs[NB*CR];
    int tid = threadIdx.x;
    for (int i = tid; i < NB*CC; i += 256){
        avg_s[i] = g_chansum[i]*(1.0f/HWn);
        mx_s[i]  = __int_as_float(g_chanmax[i]);
    }
    __syncthreads();
    if (tid < NB*CR){
        int n = tid >> 3, r = tid & 7;
        float da = 0.f, dm = 0.f;
        for (int c = 0; c < CC; ++c){
            float wv = __ldg(&w1[r*CC + c]);
            da += avg_s[n*CC + c]*wv;
            dm += mx_s[n*CC + c]*wv;
        }
        hs[tid] = fmaxf(da, 0.f) + fmaxf(dm, 0.f);
    }
    __syncthreads();
    for (int i = tid; i < NB*CC; i += 256){
        int n = i >> 7, o = i & 127;
        float y = 0.f;
        #pragma unroll
        for (int r = 0; r < CR; ++r) y += hs[n*CR + r]*__ldg(&w2[o*CR + r]);
        g_ca[i] = sigmoidf_(y);
    }
}

// ---------------- K4b: 7x7 spatial conv + sigmoid -> sa[n][p] ----------------
__global__ void k_sa(const float* __restrict__ saw){
    __shared__ float in_s[2][22][22];
    __shared__ float w_s[98];
    int n = blockIdx.y; int t = blockIdx.x;
    int ty0 = (t >> 3)*16, tx0 = (t & 7)*16;
    int tx = threadIdx.x, ty = threadIdx.y;
    int lt = ty*16 + tx;
    if (lt < 98) w_s[lt] = saw[lt];
    for (int i = lt; i < 2*22*22; i += 256){
        int ch = i / 484; int rr = i % 484; int yy = rr / 22, xx = rr % 22;
        int gy = ty0 - 3 + yy, gx = tx0 - 3 + xx;
        float v = 0.f;
        if (gy >= 0 && gy < 128 && gx >= 0 && gx < 128){
            int off = n*HWn + gy*128 + gx;
            v = (ch == 0) ? g_spsum[off]*(1.0f/CC) : g_spmax[off];
        }
        in_s[ch][yy][xx] = v;
    }
    __syncthreads();
    float acc = 0.f;
    #pragma unroll
    for (int ch = 0; ch < 2; ++ch)
        #pragma unroll
        for (int ky = 0; ky < 7; ++ky)
            #pragma unroll
            for (int kx = 0; kx < 7; ++kx)
                acc += in_s[ch][ty + ky][tx + kx]*w_s[ch*49 + ky*7 + kx];
    g_sa[n*HWn + (ty0 + ty)*128 + tx0 + tx] = sigmoidf_(acc);
}

// ---------------- K5: final blend ----------------
__global__ void k_out(const float* __restrict__ fvi, const float* __restrict__ fir,
                      float* __restrict__ out){
    int c = blockIdx.x, n = blockIdx.y, tid = threadIdx.x;
    size_t base = ((size_t)n*CC + c)*HWn;
    float wc  = g_wch[n*CC + c];
    float cav = g_ca[n*CC + c];
    const float4* v4 = (const float4*)(fvi + base);
    const float4* i4 = (const float4*)(fir + base);
    const float4* s4 = (const float4*)(g_sa + (size_t)n*HWn);
    float4* o4 = (float4*)(out + base);
    for (int i = tid; i < HWn/4; i += 256){
        float4 a = v4[i], b = i4[i], s = s4[i];
        float4 r;
        {
            float wgt = sigmoidf_(s.x*cav);
            float fv2 = fmaf(b.x, wc, a.x), fi2 = fmaf(a.x, wc, b.x);
            r.x = fi2 + wgt*(fv2 - fi2);
        }
        {
            float wgt = sigmoidf_(s.y*cav);
            float fv2 = fmaf(b.y, wc, a.y), fi2 = fmaf(a.y, wc, b.y);
            r.y = fi2 + wgt*(fv2 - fi2);
        }
        {
            float wgt = sigmoidf_(s.z*cav);
            float fv2 = fmaf(b.z, wc, a.z), fi2 = fmaf(a.z, wc, b.z);
            r.z = fi2 + wgt*(fv2 - fi2);
        }
        {
            float wgt = sigmoidf_(s.w*cav);
            float fv2 = fmaf(b.w, wc, a.w), fi2 = fmaf(a.w, wc, b.w);
            r.w = fi2 + wgt*(fv2 - fi2);
        }
        o4[i] = r;
    }
}

// ---------------- launcher ----------------
extern "C" void kernel_launch(void* const* d_in, const int* in_sizes, int n_in,
                              void* d_out, int out_size){
    const float* fvi    = (const float*)d_in[0];
    const float* fir    = (const float*)d_in[1];
    const float* ca1_w  = (const float*)d_in[2];
    const float* ca1_b  = (const float*)d_in[3];
    const float* bna_g  = (const float*)d_in[4];
    const float* bna_b  = (const float*)d_in[5];
    const float* bna_m  = (const float*)d_in[6];
    const float* bna_v  = (const float*)d_in[7];
    const float* ca2_w  = (const float*)d_in[8];
    const float* ca2_b  = (const float*)d_in[9];
    const float* bnb_g  = (const float*)d_in[10];
    const float* bnb_b  = (const float*)d_in[11];
    const float* bnb_m  = (const float*)d_in[12];
    const float* bnb_v  = (const float*)d_in[13];
    const float* cw     = (const float*)d_in[14];
    const float* c1b    = (const float*)d_in[15];
    const float* bnc_g  = (const float*)d_in[16];
    const float* bnc_b  = (const float*)d_in[17];
    const float* bnc_m  = (const float*)d_in[18];
    const float* bnc_v  = (const float*)d_in[19];
    const float* w1     = (const float*)d_in[20];
    const float* w2     = (const float*)d_in[21];
    const float* saw    = (const float*)d_in[22];

    k_pool<<<dim3(256, NB), 256>>>(fvi, fir);
    k_wch <<<NB, 256>>>(ca1_w, ca1_b, bna_g, bna_b, bna_m, bna_v,
                        ca2_w, ca2_b, bnb_g, bnb_b, bnb_m, bnb_v);
    k_mkw <<<2048, 256>>>(cw, c1b, bnc_g, bnc_b, bnc_m, bnc_v);
    k_main<<<dim3(HWn/TPIX, NB), 256>>>(fvi, fir);
    k_ca  <<<1, 256>>>(w1, w2);
    k_sa  <<<dim3(64, NB), dim3(16, 16)>>>(saw);
    k_out <<<dim3(CC, NB), 256>>>(fvi, fir, (float*)d_out);
}

// round 15
// speedup vs baseline: 2.1855x; 1.0524x over previous
#include <cuda_runtime.h>
#include <cstdint>

#define EPSV 1e-5f
#define NB   16
#define CC   128
#define C2   64
#define CR   8
#define HWn  16384
#define TPIX 128
#define KTOT 256
#define KCH  16

typedef unsigned long long u64;

__device__ __forceinline__ void cp16(void* s, const void* g){
    unsigned sa = (unsigned)__cvta_generic_to_shared(s);
    asm volatile("cp.async.cg.shared.global [%0], [%1], 16;" :: "r"(sa), "l"(g));
}
#define CP_COMMIT() asm volatile("cp.async.commit_group;")
#define CP_WAIT1()  asm volatile("cp.async.wait_group 1;")
#define CP_WAIT0()  asm volatile("cp.async.wait_group 0;")

// ---------------- device scratch (no allocations allowed) ----------------
__device__ __align__(16) float g_pooled[NB*KTOT];
__device__ __align__(16) float g_wch[NB*CC];
__device__ __align__(16) float g_W[NB*KTOT*CC];     // per-n 32768 floats, MMA-fragment order, tf32-rounded
__device__ __align__(16) float g_beta[CC];
__device__ __align__(16) float g_chansum[NB*CC];
__device__            int   g_chanmax[NB*CC];       // float bits, g >= 0
__device__ __align__(16) float g_spsum[NB*HWn];
__device__ __align__(16) float g_spmax[NB*HWn];
__device__ __align__(16) float g_ca[NB*CC];
__device__ __align__(16) float g_sa[NB*HWn];

__device__ __forceinline__ float sigmoidf_(float x){ return 1.0f/(1.0f + expf(-x)); }

// ---------------- K1: channel-wise spatial mean of [f_vi; f_ir] ----------------
__global__ void k_pool(const float* __restrict__ fvi, const float* __restrict__ fir){
    int ch = blockIdx.x; int n = blockIdx.y; int tid = threadIdx.x;
    const float* src = (ch < CC) ? (fvi + ((size_t)(n*CC + ch))*HWn)
                                 : (fir + ((size_t)(n*CC + ch - CC))*HWn);
    const float4* s4 = (const float4*)src;
    float s = 0.f;
    for (int i = tid; i < HWn/4; i += 256){ float4 v = s4[i]; s += (v.x+v.y)+(v.z+v.w); }
    for (int d = 16; d; d >>= 1) s += __shfl_xor_sync(0xffffffffu, s, d);
    __shared__ float ws[8];
    if ((tid & 31) == 0) ws[tid >> 5] = s;
    __syncthreads();
    if (tid == 0){
        float t = 0.f;
        #pragma unroll
        for (int i = 0; i < 8; ++i) t += ws[i];
        g_pooled[n*KTOT + ch] = t * (1.0f/HWn);
    }
}

// ---------------- K2a: channel-attention MLP -> wch[n][c] ----------------
__global__ void k_wch(const float* __restrict__ ca1_w, const float* __restrict__ ca1_b,
                      const float* __restrict__ bna_g, const float* __restrict__ bna_b,
                      const float* __restrict__ bna_m, const float* __restrict__ bna_v,
                      const float* __restrict__ ca2_w, const float* __restrict__ ca2_b,
                      const float* __restrict__ bnb_g, const float* __restrict__ bnb_b,
                      const float* __restrict__ bnb_m, const float* __restrict__ bnb_v){
    int n = blockIdx.x; int tid = threadIdx.x; int lane = tid & 31; int w = tid >> 5;
    __shared__ float pool_s[KTOT];
    __shared__ float h_s[C2];
    for (int i = tid; i < KTOT; i += 256) pool_s[i] = g_pooled[n*KTOT + i];
    __syncthreads();
    for (int jj = 0; jj < 8; ++jj){
        int j = w*8 + jj;
        float s = 0.f;
        for (int k = lane; k < KTOT; k += 32) s += pool_s[k]*__ldg(&ca1_w[j*KTOT + k]);
        for (int d = 16; d; d >>= 1) s += __shfl_xor_sync(0xffffffffu, s, d);
        if (lane == 0){
            float sa = bna_g[j]*rsqrtf(bna_v[j] + EPSV);
            h_s[j] = fmaxf(0.f, (s + ca1_b[j] - bna_m[j])*sa + bna_b[j]);
        }
    }
    __syncthreads();
    if (tid < CC){
        int o = tid; float s = 0.f;
        #pragma unroll 8
        for (int j = 0; j < C2; ++j) s += h_s[j]*__ldg(&ca2_w[o*C2 + j]);
        float sb = bnb_g[o]*rsqrtf(bnb_v[o] + EPSV);
        g_wch[n*CC + o] = sigmoidf_((s + ca2_b[o] - bnb_m[o])*sb + bnb_b[o]);
    }
}

// ---- K2b: effective weights -> tf32-rounded, MMA A-fragment order ----
// per n: [chunk c(16)][s(2)][mt(8)][lane(32)][elem(4)]; elem: a0..a3 of m16n8k8
__global__ void k_mkw(const float* __restrict__ cw, const float* __restrict__ c1b,
                      const float* __restrict__ bnc_g, const float* __restrict__ bnc_b,
                      const float* __restrict__ bnc_m, const float* __restrict__ bnc_v){
    int idx = blockIdx.x*256 + threadIdx.x;           // 524288 threads exactly
    int o = idx & 127; int k = (idx >> 7) & 255; int n = idx >> 15;
    float sc = bnc_g[o]*rsqrtf(bnc_v[o] + EPSV);
    int c = k & 127;
    float w1v = __ldg(&cw[o*KTOT + c]);
    float w2v = __ldg(&cw[o*KTOT + CC + c]);
    float wc  = __ldg(&g_wch[n*CC + c]);
    float val = (k < CC) ? sc*(w1v + wc*w2v) : sc*(w2v + wc*w1v);
    uint32_t tv; asm("cvt.rna.tf32.f32 %0, %1;" : "=r"(tv) : "f"(val));
    int ch  = k >> 4;                 // chunk
    int s   = (k >> 3) & 1;
    int klo = k & 3, khi = (k >> 2) & 1;
    int mt  = o >> 4;
    int rlo = o & 7, rhi = (o >> 3) & 1;
    int lane = rlo*4 + klo, elem = khi*2 + rhi;
    g_W[(size_t)n*32768 + ch*2048 + ((s*8 + mt)*32 + lane)*4 + elem] = __uint_as_float(tv);
    if (idx < CC){
        float s2 = bnc_g[idx]*rsqrtf(bnc_v[idx] + EPSV);
        g_beta[idx] = bnc_b[idx] + s2*(c1b[idx] - bnc_m[idx]);
    }
    if (idx < NB*CC){ g_chansum[idx] = 0.f; g_chanmax[idx] = 0; }
}

// -------- K3: tf32 mma.sync GEMM, D[128o x 128px] per CTA, fused reductions --------
// 3-stage cp.async pipeline, one barrier per chunk
__global__ __launch_bounds__(256,2) void k_main(const float* __restrict__ fvi,
                                                const float* __restrict__ fir){
    __shared__ __align__(16) float sb[12288];     // 3 bufs x [W 2048][B 2048]
    __shared__ float cs[CC]; __shared__ int cmi[CC];
    __shared__ float psp[2][TPIX], pmp[2][TPIX];

    int tid = threadIdx.x; int w = tid >> 5, lane = tid & 31;
    int klo = lane & 3, pxl = lane >> 2;
    int ob = (w & 1)*64, pb = (w >> 1)*32;
    int n = blockIdx.y; int p0 = blockIdx.x * TPIX;
    const float* fvin = fvi + (size_t)n*CC*HWn + p0;
    const float* firn = fir + (size_t)n*CC*HWn + p0;
    const float* Wn = g_W + (size_t)n*32768;

    if (tid < CC){ cs[tid] = 0.f; cmi[tid] = 0; }

    float acc[4][4][4];
    #pragma unroll
    for (int i = 0; i < 4; ++i)
        #pragma unroll
        for (int j = 0; j < 4; ++j)
            #pragma unroll
            for (int e = 0; e < 4; ++e) acc[i][j][e] = 0.f;

    auto load_chunk = [&](int c, int buf){
        float* wd = sb + buf*4096;
        const float* ws = Wn + c*2048;
        cp16(wd + tid*4,        ws + tid*4);
        cp16(wd + (tid+256)*4,  ws + (tid+256)*4);
        float* bd = sb + buf*4096 + 2048;
        #pragma unroll
        for (int i = 0; i < 2; ++i){
            int slot = tid + 256*i;              // 0..511 16B slots
            int k = slot >> 5; int px0 = (slot & 31) << 2;
            int chn = c*KCH + k;
            const float* src = (chn < CC) ? (fvin + (size_t)chn*HWn + px0)
                                          : (firn + (size_t)(chn - CC)*HWn + px0);
            cp16(bd + k*128 + (px0 ^ ((k & 3) << 3)), src);
        }
    };

    load_chunk(0, 0); CP_COMMIT();
    load_chunk(1, 1); CP_COMMIT();
    #pragma unroll
    for (int c = 0; c < 16; ++c){
        int buf = c % 3;
        if (c < 15) CP_WAIT1(); else CP_WAIT0();   // group c complete
        __syncthreads();                           // data visible + compute c-1 retired
        if (c < 14){ load_chunk(c + 2, (c + 2) % 3); CP_COMMIT(); }
        const float* Wsb = sb + buf*4096;
        const float* Fsb = Wsb + 2048;
        #pragma unroll
        for (int s = 0; s < 2; ++s){
            uint32_t a[4][4];
            #pragma unroll
            for (int mt = 0; mt < 4; ++mt){
                float4 av = *(const float4*)&Wsb[((s*8 + (w & 1)*4 + mt)*32 + lane)*4];
                a[mt][0] = __float_as_uint(av.x); a[mt][1] = __float_as_uint(av.y);
                a[mt][2] = __float_as_uint(av.z); a[mt][3] = __float_as_uint(av.w);
            }
            uint32_t b[4][2];
            #pragma unroll
            for (int nt = 0; nt < 4; ++nt){
                int xo = (pb + nt*8 + pxl) ^ (klo << 3);
                b[nt][0] = __float_as_uint(Fsb[(s*8 + klo)*128 + xo]);
                b[nt][1] = __float_as_uint(Fsb[(s*8 + klo + 4)*128 + xo]);
            }
            #pragma unroll
            for (int mt = 0; mt < 4; ++mt)
                #pragma unroll
                for (int nt = 0; nt < 4; ++nt)
                    asm("mma.sync.aligned.m16n8k8.row.col.f32.tf32.tf32.f32 "
                        "{%0,%1,%2,%3},{%4,%5,%6,%7},{%8,%9},{%0,%1,%2,%3};"
                        : "+f"(acc[mt][nt][0]), "+f"(acc[mt][nt][1]),
                          "+f"(acc[mt][nt][2]), "+f"(acc[mt][nt][3])
                        : "r"(a[mt][0]), "r"(a[mt][1]), "r"(a[mt][2]), "r"(a[mt][3]),
                          "r"(b[nt][0]), "r"(b[nt][1]));
        }
    }
    __syncthreads();   // all compute done before epilogue shared-atomics ordering

    // ---- epilogue: relu(acc+beta) in-place ----
    #pragma unroll
    for (int mt = 0; mt < 4; ++mt){
        float b0 = __ldg(&g_beta[ob + mt*16 + pxl]);
        float b1 = __ldg(&g_beta[ob + mt*16 + pxl + 8]);
        #pragma unroll
        for (int nt = 0; nt < 4; ++nt){
            acc[mt][nt][0] = fmaxf(acc[mt][nt][0] + b0, 0.f);
            acc[mt][nt][1] = fmaxf(acc[mt][nt][1] + b0, 0.f);
            acc[mt][nt][2] = fmaxf(acc[mt][nt][2] + b1, 0.f);
            acc[mt][nt][3] = fmaxf(acc[mt][nt][3] + b1, 0.f);
        }
    }
    // channel partials: rows r=pxl (+8) per mt; reduce over cols (lanes xor 1,2)
    {
        float rs[8], rm[8];
        #pragma unroll
        for (int mt = 0; mt < 4; ++mt){
            float s0 = 0.f, s1 = 0.f, m0 = 0.f, m1 = 0.f;
            #pragma unroll
            for (int nt = 0; nt < 4; ++nt){
                s0 += acc[mt][nt][0] + acc[mt][nt][1];
                s1 += acc[mt][nt][2] + acc[mt][nt][3];
                m0 = fmaxf(m0, fmaxf(acc[mt][nt][0], acc[mt][nt][1]));
                m1 = fmaxf(m1, fmaxf(acc[mt][nt][2], acc[mt][nt][3]));
            }
            rs[mt*2] = s0; rs[mt*2+1] = s1; rm[mt*2] = m0; rm[mt*2+1] = m1;
        }
        #pragma unroll
        for (int i = 0; i < 8; ++i){
            rs[i] += __shfl_xor_sync(0xffffffffu, rs[i], 1);
            rs[i] += __shfl_xor_sync(0xffffffffu, rs[i], 2);
            rm[i] = fmaxf(rm[i], __shfl_xor_sync(0xffffffffu, rm[i], 1));
            rm[i] = fmaxf(rm[i], __shfl_xor_sync(0xffffffffu, rm[i], 2));
        }
        if (klo == 0){
            #pragma unroll
            for (int mt = 0; mt < 4; ++mt)
                #pragma unroll
                for (int h = 0; h < 2; ++h){
                    int o = ob + mt*16 + h*8 + pxl;
                    atomicAdd(&cs[o], rs[mt*2 + h]);
                    atomicMax(&cmi[o], __float_as_int(rm[mt*2 + h]));
                }
        }
    }
    // px partials: cols 2*klo+j per nt; reduce over rows (lanes xor 4,8,16)
    {
        float qs[8], qm[8];
        #pragma unroll
        for (int nt = 0; nt < 4; ++nt)
            #pragma unroll
            for (int j = 0; j < 2; ++j){
                float s = 0.f, m = 0.f;
                #pragma unroll
                for (int mt = 0; mt < 4; ++mt){
                    s += acc[mt][nt][j] + acc[mt][nt][j+2];
                    m = fmaxf(m, fmaxf(acc[mt][nt][j], acc[mt][nt][j+2]));
                }
                qs[nt*2 + j] = s; qm[nt*2 + j] = m;
            }
        #pragma unroll
        for (int i = 0; i < 8; ++i){
            qs[i] += __shfl_xor_sync(0xffffffffu, qs[i], 4);
            qs[i] += __shfl_xor_sync(0xffffffffu, qs[i], 8);
            qs[i] += __shfl_xor_sync(0xffffffffu, qs[i], 16);
            qm[i] = fmaxf(qm[i], __shfl_xor_sync(0xffffffffu, qm[i], 4));
            qm[i] = fmaxf(qm[i], __shfl_xor_sync(0xffffffffu, qm[i], 8));
            qm[i] = fmaxf(qm[i], __shfl_xor_sync(0xffffffffu, qm[i], 16));
        }
        if (lane < 4){
            #pragma unroll
            for (int nt = 0; nt < 4; ++nt)
                #pragma unroll
                for (int j = 0; j < 2; ++j){
                    int col = pb + nt*8 + 2*lane + j;
                    psp[w & 1][col] = qs[nt*2 + j];
                    pmp[w & 1][col] = qm[nt*2 + j];
                }
        }
    }
    __syncthreads();
    if (tid < TPIX){
        g_spsum[n*HWn + p0 + tid] = psp[0][tid] + psp[1][tid];
        g_spmax[n*HWn + p0 + tid] = fmaxf(pmp[0][tid], pmp[1][tid]);
    } else {
        int o = tid - TPIX;
        atomicAdd(&g_chansum[n*CC + o], cs[o]);
        atomicMax(&g_chanmax[n*CC + o], cmi[o]);
    }
}

// ---------------- K4a: CBAM channel attention -> ca[n][o] ----------------
__global__ void k_ca(const float* __restrict__ w1, const float* __restrict__ w2){
    __shared__ float avg_s[NB*CC], mx_s[NB*CC], hs[NB*CR];
    int tid = threadIdx.x;
    for (int i = tid; i < NB*CC; i += 256){
        avg_s[i] = g_chansum[i]*(1.0f/HWn);
        mx_s[i]  = __int_as_float(g_chanmax[i]);
    }
    __syncthreads();
    if (tid < NB*CR){
        int n = tid >> 3, r = tid & 7;
        float da = 0.f, dm = 0.f;
        for (int c = 0; c < CC; ++c){
            float wv = __ldg(&w1[r*CC + c]);
            da += avg_s[n*CC + c]*wv;
            dm += mx_s[n*CC + c]*wv;
        }
        hs[tid] = fmaxf(da, 0.f) + fmaxf(dm, 0.f);
    }
    __syncthreads();
    for (int i = tid; i < NB*CC; i += 256){
        int n = i >> 7, o = i & 127;
        float y = 0.f;
        #pragma unroll
        for (int r = 0; r < CR; ++r) y += hs[n*CR + r]*__ldg(&w2[o*CR + r]);
        g_ca[i] = sigmoidf_(y);
    }
}

// ---------------- K4b: 7x7 spatial conv + sigmoid -> sa[n][p] ----------------
__global__ void k_sa(const float* __restrict__ saw){
    __shared__ float in_s[2][22][22];
    __shared__ float w_s[98];
    int n = blockIdx.y; int t = blockIdx.x;
    int ty0 = (t >> 3)*16, tx0 = (t & 7)*16;
    int tx = threadIdx.x, ty = threadIdx.y;
    int lt = ty*16 + tx;
    if (lt < 98) w_s[lt] = saw[lt];
    for (int i = lt; i < 2*22*22; i += 256){
        int ch = i / 484; int rr = i % 484; int yy = rr / 22, xx = rr % 22;
        int gy = ty0 - 3 + yy, gx = tx0 - 3 + xx;
        float v = 0.f;
        if (gy >= 0 && gy < 128 && gx >= 0 && gx < 128){
            int off = n*HWn + gy*128 + gx;
            v = (ch == 0) ? g_spsum[off]*(1.0f/CC) : g_spmax[off];
        }
        in_s[ch][yy][xx] = v;
    }
    __syncthreads();
    float acc = 0.f;
    #pragma unroll
    for (int ch = 0; ch < 2; ++ch)
        #pragma unroll
        for (int ky = 0; ky < 7; ++ky)
            #pragma unroll
            for (int kx = 0; kx < 7; ++kx)
                acc += in_s[ch][ty + ky][tx + kx]*w_s[ch*49 + ky*7 + kx];
    g_sa[n*HWn + (ty0 + ty)*128 + tx0 + tx] = sigmoidf_(acc);
}

// ---------------- K5: final blend ----------------
__global__ void k_out(const float* __restrict__ fvi, const float* __restrict__ fir,
                      float* __restrict__ out){
    int c = blockIdx.x, n = blockIdx.y, tid = threadIdx.x;
    size_t base = ((size_t)n*CC + c)*HWn;
    float wc  = g_wch[n*CC + c];
    float cav = g_ca[n*CC + c];
    const float4* v4 = (const float4*)(fvi + base);
    const float4* i4 = (const float4*)(fir + base);
    const float4* s4 = (const float4*)(g_sa + (size_t)n*HWn);
    float4* o4 = (float4*)(out + base);
    for (int i = tid; i < HWn/4; i += 256){
        float4 a = v4[i], b = i4[i], s = s4[i];
        float4 r;
        {
            float wgt = sigmoidf_(s.x*cav);
            float fv2 = fmaf(b.x, wc, a.x), fi2 = fmaf(a.x, wc, b.x);
            r.x = fi2 + wgt*(fv2 - fi2);
        }
        {
            float wgt = sigmoidf_(s.y*cav);
            float fv2 = fmaf(b.y, wc, a.y), fi2 = fmaf(a.y, wc, b.y);
            r.y = fi2 + wgt*(fv2 - fi2);
        }
        {
            float wgt = sigmoidf_(s.z*cav);
            float fv2 = fmaf(b.z, wc, a.z), fi2 = fmaf(a.z, wc, b.z);
            r.z = fi2 + wgt*(fv2 - fi2);
        }
        {
            float wgt = sigmoidf_(s.w*cav);
            float fv2 = fmaf(b.w, wc, a.w), fi2 = fmaf(a.w, wc, b.w);
            r.w = fi2 + wgt*(fv2 - fi2);
        }
        o4[i] = r;
    }
}

// ---------------- launcher ----------------
extern "C" void kernel_launch(void* const* d_in, const int* in_sizes, int n_in,
                              void* d_out, int out_size){
    const float* fvi    = (const float*)d_in[0];
    const float* fir    = (const float*)d_in[1];
    const float* ca1_w  = (const float*)d_in[2];
    const float* ca1_b  = (const float*)d_in[3];
    const float* bna_g  = (const float*)d_in[4];
    const float* bna_b  = (const float*)d_in[5];
    const float* bna_m  = (const float*)d_in[6];
    const float* bna_v  = (const float*)d_in[7];
    const float* ca2_w  = (const float*)d_in[8];
    const float* ca2_b  = (const float*)d_in[9];
    const float* bnb_g  = (const float*)d_in[10];
    const float* bnb_b  = (const float*)d_in[11];
    const float* bnb_m  = (const float*)d_in[12];
    const float* bnb_v  = (const float*)d_in[13];
    const float* cw     = (const float*)d_in[14];
    const float* c1b    = (const float*)d_in[15];
    const float* bnc_g  = (const float*)d_in[16];
    const float* bnc_b  = (const float*)d_in[17];
    const float* bnc_m  = (const float*)d_in[18];
    const float* bnc_v  = (const float*)d_in[19];
    const float* w1     = (const float*)d_in[20];
    const float* w2     = (const float*)d_in[21];
    const float* saw    = (const float*)d_in[22];

    k_pool<<<dim3(256, NB), 256>>>(fvi, fir);
    k_wch <<<NB, 256>>>(ca1_w, ca1_b, bna_g, bna_b, bna_m, bna_v,
                        ca2_w, ca2_b, bnb_g, bnb_b, bnb_m, bnb_v);
    k_mkw <<<2048, 256>>>(cw, c1b, bnc_g, bnc_b, bnc_m, bnc_v);
    k_main<<<dim3(HWn/TPIX, NB), 256>>>(fvi, fir);
    k_ca  <<<1, 256>>>(w1, w2);
    k_sa  <<<dim3(64, NB), dim3(16, 16)>>>(saw);
    k_out <<<dim3(CC, NB), 256>>>(fvi, fir, (float*)d_out);
}

// round 16
// speedup vs baseline: 2.2811x; 1.0437x over previous
#include <cuda_runtime.h>
#include <cuda_fp16.h>
#include <cstdint>

#define EPSV 1e-5f
#define NB   16
#define CC   128
#define C2   64
#define CR   8
#define HWn  16384
#define TPIX 128
#define KTOT 256

typedef unsigned long long u64;

__device__ __forceinline__ void cp16(void* s, const void* g){
    unsigned sa = (unsigned)__cvta_generic_to_shared(s);
    asm volatile("cp.async.cg.shared.global [%0], [%1], 16;" :: "r"(sa), "l"(g));
}
#define CP_COMMIT() asm volatile("cp.async.commit_group;")
#define CP_WAIT1()  asm volatile("cp.async.wait_group 1;")
#define CP_WAIT0()  asm volatile("cp.async.wait_group 0;")

// ---------------- device scratch (no allocations allowed) ----------------
__device__ __align__(16) float  g_pooled[NB*KTOT];
__device__ __align__(16) float  g_wch[NB*CC];
__device__ __align__(16) __half g_h[(size_t)NB*KTOT*HWn];   // fp16 copy of [f_vi;f_ir]
__device__ __align__(16) __half g_Wh[NB*32768];             // fp16 W, m16n8k16 A-fragment order
__device__ __align__(16) float  g_beta[CC];
__device__ __align__(16) float  g_chansum[NB*CC];
__device__             int    g_chanmax[NB*CC];             // float bits, g >= 0
__device__ __align__(16) float  g_spsum[NB*HWn];
__device__ __align__(16) float  g_spmax[NB*HWn];
__device__ __align__(16) float  g_ca[NB*CC];
__device__ __align__(16) float  g_sa[NB*HWn];

__device__ __forceinline__ float sigmoidf_(float x){ return 1.0f/(1.0f + expf(-x)); }

// ------- K1: channel-wise spatial mean of [f_vi; f_ir] + fp16 copy -------
__global__ void k_pool(const float* __restrict__ fvi, const float* __restrict__ fir){
    int ch = blockIdx.x; int n = blockIdx.y; int tid = threadIdx.x;
    const float* src = (ch < CC) ? (fvi + ((size_t)(n*CC + ch))*HWn)
                                 : (fir + ((size_t)(n*CC + ch - CC))*HWn);
    const float4* s4 = (const float4*)src;
    __half* hdst = g_h + ((size_t)(n*KTOT + ch))*HWn;
    float s = 0.f;
    for (int i = tid; i < HWn/4; i += 256){
        float4 v = s4[i];
        s += (v.x+v.y)+(v.z+v.w);
        __half2 h0 = __floats2half2_rn(v.x, v.y);
        __half2 h1 = __floats2half2_rn(v.z, v.w);
        uint2 pk; pk.x = *(unsigned*)&h0; pk.y = *(unsigned*)&h1;
        *(uint2*)(hdst + i*4) = pk;
    }
    for (int d = 16; d; d >>= 1) s += __shfl_xor_sync(0xffffffffu, s, d);
    __shared__ float ws[8];
    if ((tid & 31) == 0) ws[tid >> 5] = s;
    __syncthreads();
    if (tid == 0){
        float t = 0.f;
        #pragma unroll
        for (int i = 0; i < 8; ++i) t += ws[i];
        g_pooled[n*KTOT + ch] = t * (1.0f/HWn);
    }
}

// ---------------- K2a: channel-attention MLP -> wch[n][c] ----------------
__global__ void k_wch(const float* __restrict__ ca1_w, const float* __restrict__ ca1_b,
                      const float* __restrict__ bna_g, const float* __restrict__ bna_b,
                      const float* __restrict__ bna_m, const float* __restrict__ bna_v,
                      const float* __restrict__ ca2_w, const float* __restrict__ ca2_b,
                      const float* __restrict__ bnb_g, const float* __restrict__ bnb_b,
                      const float* __restrict__ bnb_m, const float* __restrict__ bnb_v){
    int n = blockIdx.x; int tid = threadIdx.x; int lane = tid & 31; int w = tid >> 5;
    __shared__ float pool_s[KTOT];
    __shared__ float h_s[C2];
    for (int i = tid; i < KTOT; i += 256) pool_s[i] = g_pooled[n*KTOT + i];
    __syncthreads();
    for (int jj = 0; jj < 8; ++jj){
        int j = w*8 + jj;
        float s = 0.f;
        for (int k = lane; k < KTOT; k += 32) s += pool_s[k]*__ldg(&ca1_w[j*KTOT + k]);
        for (int d = 16; d; d >>= 1) s += __shfl_xor_sync(0xffffffffu, s, d);
        if (lane == 0){
            float sa = bna_g[j]*rsqrtf(bna_v[j] + EPSV);
            h_s[j] = fmaxf(0.f, (s + ca1_b[j] - bna_m[j])*sa + bna_b[j]);
        }
    }
    __syncthreads();
    if (tid < CC){
        int o = tid; float s = 0.f;
        #pragma unroll 8
        for (int j = 0; j < C2; ++j) s += h_s[j]*__ldg(&ca2_w[o*C2 + j]);
        float sb = bnb_g[o]*rsqrtf(bnb_v[o] + EPSV);
        g_wch[n*CC + o] = sigmoidf_((s + ca2_b[o] - bnb_m[o])*sb + bnb_b[o]);
    }
}

// ---- K2b: effective weights -> fp16, m16n8k16 A-fragment order ----
// per n: [chunk(16)][mt(8)][lane(32)][reg(4)][half(2)]
__global__ void k_mkw(const float* __restrict__ cw, const float* __restrict__ c1b,
                      const float* __restrict__ bnc_g, const float* __restrict__ bnc_b,
                      const float* __restrict__ bnc_m, const float* __restrict__ bnc_v){
    int idx = blockIdx.x*256 + threadIdx.x;           // 524288 threads exactly
    int o = idx & 127; int k = (idx >> 7) & 255; int n = idx >> 15;
    float sc = bnc_g[o]*rsqrtf(bnc_v[o] + EPSV);
    int c = k & 127;
    float w1v = __ldg(&cw[o*KTOT + c]);
    float w2v = __ldg(&cw[o*KTOT + CC + c]);
    float wc  = __ldg(&g_wch[n*CC + c]);
    float val = (k < CC) ? sc*(w1v + wc*w2v) : sc*(w2v + wc*w1v);
    int chunk = k >> 4, e = k & 15;
    int mt = o >> 4, r = o & 15, rlo = r & 7, rhi = r >> 3;
    int lane = rlo*4 + ((e & 7) >> 1);
    int reg  = (e >> 3)*2 + rhi;
    size_t off = ((((size_t)n*16 + chunk)*8 + mt)*32 + lane)*8 + reg*2 + (e & 1);
    g_Wh[off] = __float2half_rn(val);
    if (idx < CC){
        float s2 = bnc_g[idx]*rsqrtf(bnc_v[idx] + EPSV);
        g_beta[idx] = bnc_b[idx] + s2*(c1b[idx] - bnc_m[idx]);
    }
    if (idx < NB*CC){ g_chansum[idx] = 0.f; g_chanmax[idx] = 0; }
}

// -------- K3: fp16 mma.sync GEMM, D[128o x 128px] per CTA, fused reductions --------
// 3-stage cp.async pipeline, one barrier per chunk; B via ldmatrix.x4.trans
__global__ __launch_bounds__(256,2) void k_main(void){
    __shared__ __align__(128) unsigned char sbm[3*8192];   // buf: [W 4KB][B 4KB]
    __shared__ float cs[CC]; __shared__ int cmi[CC];
    __shared__ float psp[2][TPIX], pmp[2][TPIX];

    int tid = threadIdx.x; int w = tid >> 5, lane = tid & 31;
    int klo = lane & 3, pxl = lane >> 2;
    int ob = (w & 1)*64, pb = (w >> 1)*32;
    int n = blockIdx.y; int p0 = blockIdx.x * TPIX;

    if (tid < CC){ cs[tid] = 0.f; cmi[tid] = 0; }

    float acc[4][4][4];
    #pragma unroll
    for (int i = 0; i < 4; ++i)
        #pragma unroll
        for (int j = 0; j < 4; ++j)
            #pragma unroll
            for (int e = 0; e < 4; ++e) acc[i][j][e] = 0.f;

    const unsigned char* wg = (const unsigned char*)(g_Wh + (size_t)n*32768);
    // B load slot: k = tid>>4 (0..15), px0 = (tid&15)*8
    int bk = tid >> 4, bpx = (tid & 15)*8;
    unsigned boff = (unsigned)(bk*256 + bpx*2) ^ (unsigned)((bk & 7) << 4);
    const __half* bsrc0 = g_h + ((size_t)n*KTOT + bk)*HWn + p0 + bpx;

    auto load_chunk = [&](int c, int buf){
        unsigned char* base = sbm + buf*8192;
        cp16(base + tid*16, wg + c*4096 + tid*16);
        cp16(base + 4096 + boff, bsrc0 + (size_t)c*16*HWn);
    };

    load_chunk(0, 0); CP_COMMIT();
    load_chunk(1, 1); CP_COMMIT();
    int bmi = lane >> 3, brow = lane & 7;
    int bkk = brow + (bmi & 1)*8;
    #pragma unroll
    for (int c = 0; c < 16; ++c){
        int buf = c % 3;
        if (c < 15) CP_WAIT1(); else CP_WAIT0();   // group c complete
        __syncthreads();                           // data visible + compute c-1 retired
        if (c < 14){ load_chunk(c + 2, (c + 2) % 3); CP_COMMIT(); }
        const unsigned char* wb = sbm + buf*8192;
        const unsigned char* bb = wb + 4096;
        uint32_t a[4][4];
        #pragma unroll
        for (int mt = 0; mt < 4; ++mt){
            uint4 av = *(const uint4*)(wb + (((w & 1)*4 + mt)*32 + lane)*16);
            a[mt][0] = av.x; a[mt][1] = av.y; a[mt][2] = av.z; a[mt][3] = av.w;
        }
        uint32_t bfr[2][4];
        #pragma unroll
        for (int ntp = 0; ntp < 2; ++ntp){
            int pxb = pb + ntp*16 + (bmi >> 1)*8;
            unsigned off = (unsigned)(bkk*256 + pxb*2) ^ (unsigned)((bkk & 7) << 4);
            unsigned addr = (unsigned)__cvta_generic_to_shared(bb + off);
            asm volatile("ldmatrix.sync.aligned.m8n8.x4.trans.shared.b16 {%0,%1,%2,%3}, [%4];"
                : "=r"(bfr[ntp][0]), "=r"(bfr[ntp][1]), "=r"(bfr[ntp][2]), "=r"(bfr[ntp][3])
                : "r"(addr));
        }
        #pragma unroll
        for (int mt = 0; mt < 4; ++mt)
            #pragma unroll
            for (int nt = 0; nt < 4; ++nt){
                uint32_t b0 = bfr[nt >> 1][(nt & 1)*2];
                uint32_t b1 = bfr[nt >> 1][(nt & 1)*2 + 1];
                asm("mma.sync.aligned.m16n8k16.row.col.f32.f16.f16.f32 "
                    "{%0,%1,%2,%3},{%4,%5,%6,%7},{%8,%9},{%0,%1,%2,%3};"
                    : "+f"(acc[mt][nt][0]), "+f"(acc[mt][nt][1]),
                      "+f"(acc[mt][nt][2]), "+f"(acc[mt][nt][3])
                    : "r"(a[mt][0]), "r"(a[mt][1]), "r"(a[mt][2]), "r"(a[mt][3]),
                      "r"(b0), "r"(b1));
            }
    }
    __syncthreads();   // all compute done before epilogue shared-atomics ordering

    // ---- epilogue: relu(acc+beta) in-place ----
    #pragma unroll
    for (int mt = 0; mt < 4; ++mt){
        float b0 = __ldg(&g_beta[ob + mt*16 + pxl]);
        float b1 = __ldg(&g_beta[ob + mt*16 + pxl + 8]);
        #pragma unroll
        for (int nt = 0; nt < 4; ++nt){
            acc[mt][nt][0] = fmaxf(acc[mt][nt][0] + b0, 0.f);
            acc[mt][nt][1] = fmaxf(acc[mt][nt][1] + b0, 0.f);
            acc[mt][nt][2] = fmaxf(acc[mt][nt][2] + b1, 0.f);
            acc[mt][nt][3] = fmaxf(acc[mt][nt][3] + b1, 0.f);
        }
    }
    // channel partials: rows r=pxl (+8) per mt; reduce over cols (lanes xor 1,2)
    {
        float rs[8], rm[8];
        #pragma unroll
        for (int mt = 0; mt < 4; ++mt){
            float s0 = 0.f, s1 = 0.f, m0 = 0.f, m1 = 0.f;
            #pragma unroll
            for (int nt = 0; nt < 4; ++nt){
                s0 += acc[mt][nt][0] + acc[mt][nt][1];
                s1 += acc[mt][nt][2] + acc[mt][nt][3];
                m0 = fmaxf(m0, fmaxf(acc[mt][nt][0], acc[mt][nt][1]));
                m1 = fmaxf(m1, fmaxf(acc[mt][nt][2], acc[mt][nt][3]));
            }
            rs[mt*2] = s0; rs[mt*2+1] = s1; rm[mt*2] = m0; rm[mt*2+1] = m1;
        }
        #pragma unroll
        for (int i = 0; i < 8; ++i){
            rs[i] += __shfl_xor_sync(0xffffffffu, rs[i], 1);
            rs[i] += __shfl_xor_sync(0xffffffffu, rs[i], 2);
            rm[i] = fmaxf(rm[i], __shfl_xor_sync(0xffffffffu, rm[i], 1));
            rm[i] = fmaxf(rm[i], __shfl_xor_sync(0xffffffffu, rm[i], 2));
        }
        if (klo == 0){
            #pragma unroll
            for (int mt = 0; mt < 4; ++mt)
                #pragma unroll
                for (int h = 0; h < 2; ++h){
                    int o = ob + mt*16 + h*8 + pxl;
                    atomicAdd(&cs[o], rs[mt*2 + h]);
                    atomicMax(&cmi[o], __float_as_int(rm[mt*2 + h]));
                }
        }
    }
    // px partials: cols 2*klo+j per nt; reduce over rows (lanes xor 4,8,16)
    {
        float qs[8], qm[8];
        #pragma unroll
        for (int nt = 0; nt < 4; ++nt)
            #pragma unroll
            for (int j = 0; j < 2; ++j){
                float s = 0.f, m = 0.f;
                #pragma unroll
                for (int mt = 0; mt < 4; ++mt){
                    s += acc[mt][nt][j] + acc[mt][nt][j+2];
                    m = fmaxf(m, fmaxf(acc[mt][nt][j], acc[mt][nt][j+2]));
                }
                qs[nt*2 + j] = s; qm[nt*2 + j] = m;
            }
        #pragma unroll
        for (int i = 0; i < 8; ++i){
            qs[i] += __shfl_xor_sync(0xffffffffu, qs[i], 4);
            qs[i] += __shfl_xor_sync(0xffffffffu, qs[i], 8);
            qs[i] += __shfl_xor_sync(0xffffffffu, qs[i], 16);
            qm[i] = fmaxf(qm[i], __shfl_xor_sync(0xffffffffu, qm[i], 4));
            qm[i] = fmaxf(qm[i], __shfl_xor_sync(0xffffffffu, qm[i], 8));
            qm[i] = fmaxf(qm[i], __shfl_xor_sync(0xffffffffu, qm[i], 16));
        }
        if (lane < 4){
            #pragma unroll
            for (int nt = 0; nt < 4; ++nt)
                #pragma unroll
                for (int j = 0; j < 2; ++j){
                    int col = pb + nt*8 + 2*lane + j;
                    psp[w & 1][col] = qs[nt*2 + j];
                    pmp[w & 1][col] = qm[nt*2 + j];
                }
        }
    }
    __syncthreads();
    if (tid < TPIX){
        g_spsum[n*HWn + p0 + tid] = psp[0][tid] + psp[1][tid];
        g_spmax[n*HWn + p0 + tid] = fmaxf(pmp[0][tid], pmp[1][tid]);
    } else {
        int o = tid - TPIX;
        atomicAdd(&g_chansum[n*CC + o], cs[o]);
        atomicMax(&g_chanmax[n*CC + o], cmi[o]);
    }
}

// ---------------- K4a: CBAM channel attention -> ca[n][o] ----------------
__global__ void k_ca(const float* __restrict__ w1, const float* __restrict__ w2){
    __shared__ float avg_s[NB*CC], mx_s[NB*CC], hs[NB*CR];
    int tid = threadIdx.x;
    for (int i = tid; i < NB*CC; i += 256){
        avg_s[i] = g_chansum[i]*(1.0f/HWn);
        mx_s[i]  = __int_as_float(g_chanmax[i]);
    }
    __syncthreads();
    if (tid < NB*CR){
        int n = tid >> 3, r = tid & 7;
        float da = 0.f, dm = 0.f;
        for (int c = 0; c < CC; ++c){
            float wv = __ldg(&w1[r*CC + c]);
            da += avg_s[n*CC + c]*wv;
            dm += mx_s[n*CC + c]*wv;
        }
        hs[tid] = fmaxf(da, 0.f) + fmaxf(dm, 0.f);
    }
    __syncthreads();
    for (int i = tid; i < NB*CC; i += 256){
        int n = i >> 7, o = i & 127;
        float y = 0.f;
        #pragma unroll
        for (int r = 0; r < CR; ++r) y += hs[n*CR + r]*__ldg(&w2[o*CR + r]);
        g_ca[i] = sigmoidf_(y);
    }
}

// ---------------- K4b: 7x7 spatial conv + sigmoid -> sa[n][p] ----------------
__global__ void k_sa(const float* __restrict__ saw){
    __shared__ float in_s[2][22][22];
    __shared__ float w_s[98];
    int n = blockIdx.y; int t = blockIdx.x;
    int ty0 = (t >> 3)*16, tx0 = (t & 7)*16;
    int tx = threadIdx.x, ty = threadIdx.y;
    int lt = ty*16 + tx;
    if (lt < 98) w_s[lt] = saw[lt];
    for (int i = lt; i < 2*22*22; i += 256){
        int ch = i / 484; int rr = i % 484; int yy = rr / 22, xx = rr % 22;
        int gy = ty0 - 3 + yy, gx = tx0 - 3 + xx;
        float v = 0.f;
        if (gy >= 0 && gy < 128 && gx >= 0 && gx < 128){
            int off = n*HWn + gy*128 + gx;
            v = (ch == 0) ? g_spsum[off]*(1.0f/CC) : g_spmax[off];
        }
        in_s[ch][yy][xx] = v;
    }
    __syncthreads();
    float acc = 0.f;
    #pragma unroll
    for (int ch = 0; ch < 2; ++ch)
        #pragma unroll
        for (int ky = 0; ky < 7; ++ky)
            #pragma unroll
            for (int kx = 0; kx < 7; ++kx)
                acc += in_s[ch][ty + ky][tx + kx]*w_s[ch*49 + ky*7 + kx];
    g_sa[n*HWn + (ty0 + ty)*128 + tx0 + tx] = sigmoidf_(acc);
}

// ---------------- K5: final blend ----------------
__global__ void k_out(const float* __restrict__ fvi, const float* __restrict__ fir,
                      float* __restrict__ out){
    int c = blockIdx.x, n = blockIdx.y, tid = threadIdx.x;
    size_t base = ((size_t)n*CC + c)*HWn;
    float wc  = g_wch[n*CC + c];
    float cav = g_ca[n*CC + c];
    const float4* v4 = (const float4*)(fvi + base);
    const float4* i4 = (const float4*)(fir + base);
    const float4* s4 = (const float4*)(g_sa + (size_t)n*HWn);
    float4* o4 = (float4*)(out + base);
    for (int i = tid; i < HWn/4; i += 256){
        float4 a = v4[i], b = i4[i], s = s4[i];
        float4 r;
        {
            float wgt = sigmoidf_(s.x*cav);
            float fv2 = fmaf(b.x, wc, a.x), fi2 = fmaf(a.x, wc, b.x);
            r.x = fi2 + wgt*(fv2 - fi2);
        }
        {
            float wgt = sigmoidf_(s.y*cav);
            float fv2 = fmaf(b.y, wc, a.y), fi2 = fmaf(a.y, wc, b.y);
            r.y = fi2 + wgt*(fv2 - fi2);
        }
        {
            float wgt = sigmoidf_(s.z*cav);
            float fv2 = fmaf(b.z, wc, a.z), fi2 = fmaf(a.z, wc, b.z);
            r.z = fi2 + wgt*(fv2 - fi2);
        }
        {
            float wgt = sigmoidf_(s.w*cav);
            float fv2 = fmaf(b.w, wc, a.w), fi2 = fmaf(a.w, wc, b.w);
            r.w = fi2 + wgt*(fv2 - fi2);
        }
        o4[i] = r;
    }
}

// ---------------- launcher ----------------
extern "C" void kernel_launch(void* const* d_in, const int* in_sizes, int n_in,
                              void* d_out, int out_size){
    const float* fvi    = (const float*)d_in[0];
    const float* fir    = (const float*)d_in[1];
    const float* ca1_w  = (const float*)d_in[2];
    const float* ca1_b  = (const float*)d_in[3];
    const float* bna_g  = (const float*)d_in[4];
    const float* bna_b  = (const float*)d_in[5];
    const float* bna_m  = (const float*)d_in[6];
    const float* bna_v  = (const float*)d_in[7];
    const float* ca2_w  = (const float*)d_in[8];
    const float* ca2_b  = (const float*)d_in[9];
    const float* bnb_g  = (const float*)d_in[10];
    const float* bnb_b  = (const float*)d_in[11];
    const float* bnb_m  = (const float*)d_in[12];
    const float* bnb_v  = (const float*)d_in[13];
    const float* cw     = (const float*)d_in[14];
    const float* c1b    = (const float*)d_in[15];
    const float* bnc_g  = (const float*)d_in[16];
    const float* bnc_b  = (const float*)d_in[17];
    const float* bnc_m  = (const float*)d_in[18];
    const float* bnc_v  = (const float*)d_in[19];
    const float* w1     = (const float*)d_in[20];
    const float* w2     = (const float*)d_in[21];
    const float* saw    = (const float*)d_in[22];

    k_pool<<<dim3(256, NB), 256>>>(fvi, fir);
    k_wch <<<NB, 256>>>(ca1_w, ca1_b, bna_g, bna_b, bna_m, bna_v,
                        ca2_w, ca2_b, bnb_g, bnb_b, bnb_m, bnb_v);
    k_mkw <<<2048, 256>>>(cw, c1b, bnc_g, bnc_b, bnc_m, bnc_v);
    k_main<<<dim3(HWn/TPIX, NB), 256>>>();
    k_ca  <<<1, 256>>>(w1, w2);
    k_sa  <<<dim3(64, NB), dim3(16, 16)>>>(saw);
    k_out <<<dim3(CC, NB), 256>>>(fvi, fir, (float*)d_out);
}